// round 1
// baseline (speedup 1.0000x reference)
#include <cuda_runtime.h>
#include <math.h>

#define B_  2
#define S_  512
#define V_  32000
#define D_  768
#define F_  2048
#define L_  4
#define H_  12
#define HD_ 64
#define FCS_ 8
#define YW_ (S_ + FCS_ - 1)   /* 519 */
#define NT_ (B_ * S_)         /* 1024 rows */

// ---------------- static scratch (allocation-free rule) ----------------
__device__ float  g_h [NT_ * D_];
__device__ float  g_a [NT_ * D_];
__device__ float  g_q [NT_ * D_];
__device__ float  g_k [NT_ * D_];
__device__ float  g_v [NT_ * D_];
__device__ float  g_o [NT_ * D_];
__device__ float  g_g1[NT_ * F_];
__device__ float  g_u1[NT_ * F_];
__device__ float  g_c [NT_ * V_];      // context head logits c (131 MB)
__device__ float2 g_rope[S_ * 32];
__device__ double g_acc[4];            // [0]=softplus_sum [1]=delta [2]=nll_sum [3]=valid

// ---------------- small helpers ----------------
__device__ __forceinline__ float softplusf(float x) {
    if (x > 15.0f) return x;
    return log1pf(expf(x));
}

__global__ void zero_acc_kernel() {
    if (threadIdx.x < 4) g_acc[threadIdx.x] = 0.0;
}

// ---------------- embedding gather ----------------
__global__ void embed_kernel(const int* __restrict__ x, const float* __restrict__ emb) {
    int i = blockIdx.x * blockDim.x + threadIdx.x;
    if (i >= NT_ * D_) return;
    int row = i / D_;
    int d   = i - row * D_;
    g_h[i] = emb[(size_t)x[row] * D_ + d];
}

// ---------------- rmsnorm: out = in * rsqrt(mean(in^2)+eps) * w ----------------
__global__ void rmsnorm_kernel(const float* __restrict__ in, const float* __restrict__ w,
                               float* __restrict__ out) {
    int row = blockIdx.x;
    const float* ip = in + row * D_;
    float* op = out + row * D_;
    __shared__ float red[256];
    float ss = 0.f;
    for (int d = threadIdx.x; d < D_; d += 256) { float v = ip[d]; ss += v * v; }
    red[threadIdx.x] = ss; __syncthreads();
    for (int st = 128; st > 0; st >>= 1) {
        if (threadIdx.x < st) red[threadIdx.x] += red[threadIdx.x + st];
        __syncthreads();
    }
    float rs = rsqrtf(red[0] / (float)D_ + 1e-5f);
    for (int d = threadIdx.x; d < D_; d += 256) op[d] = ip[d] * rs * w[d];
}

// ---------------- NT GEMM: C[m,n] (op)= sum_k A[m,k]*B[n,k] ----------------
// EPI: 0=store 1=add(residual) 2=silu-store 3=mul-by-G-store
template<int EPI>
__global__ __launch_bounds__(256)
void gemm_nt(const float* __restrict__ A, const float* __restrict__ B,
             float* __restrict__ C, const float* __restrict__ G,
             int M, int N, int K) {
    __shared__ float As[16][64];
    __shared__ float Bs[16][64];
    int tid = threadIdx.x;
    int bm = blockIdx.y * 64;
    int bn = blockIdx.x * 64;
    int ty = tid >> 4, tx = tid & 15;
    int lr = tid >> 2;             // 0..63
    int lc = (tid & 3) << 2;       // 0,4,8,12
    const float* Ap = A + (size_t)(bm + lr) * K + lc;
    const float* Bp = B + (size_t)(bn + lr) * K + lc;
    float acc[4][4] = {};

    for (int k0 = 0; k0 < K; k0 += 16) {
        float4 av = *(const float4*)(Ap + k0);
        float4 bv = *(const float4*)(Bp + k0);
        As[lc + 0][lr] = av.x; As[lc + 1][lr] = av.y;
        As[lc + 2][lr] = av.z; As[lc + 3][lr] = av.w;
        Bs[lc + 0][lr] = bv.x; Bs[lc + 1][lr] = bv.y;
        Bs[lc + 2][lr] = bv.z; Bs[lc + 3][lr] = bv.w;
        __syncthreads();
#pragma unroll
        for (int k = 0; k < 16; k++) {
            float4 a4 = *(const float4*)&As[k][ty << 2];
            float4 b4 = *(const float4*)&Bs[k][tx << 2];
            float ar[4] = {a4.x, a4.y, a4.z, a4.w};
            float br[4] = {b4.x, b4.y, b4.z, b4.w};
#pragma unroll
            for (int i = 0; i < 4; i++)
#pragma unroll
                for (int j = 0; j < 4; j++)
                    acc[i][j] += ar[i] * br[j];
        }
        __syncthreads();
    }

#pragma unroll
    for (int i = 0; i < 4; i++) {
        size_t idx = (size_t)(bm + (ty << 2) + i) * N + bn + (tx << 2);
        float4 r = make_float4(acc[i][0], acc[i][1], acc[i][2], acc[i][3]);
        if (EPI == 1) {
            float4 o = *(const float4*)(C + idx);
            r.x += o.x; r.y += o.y; r.z += o.z; r.w += o.w;
        } else if (EPI == 2) {
            r.x = r.x / (1.f + expf(-r.x));
            r.y = r.y / (1.f + expf(-r.y));
            r.z = r.z / (1.f + expf(-r.z));
            r.w = r.w / (1.f + expf(-r.w));
        } else if (EPI == 3) {
            float4 gg = *(const float4*)(G + idx);
            r.x *= gg.x; r.y *= gg.y; r.z *= gg.z; r.w *= gg.w;
        }
        *(float4*)(C + idx) = r;
    }
}

// ---------------- RoPE ----------------
__global__ void rope_table_kernel() {
    int i = blockIdx.x * blockDim.x + threadIdx.x;
    if (i >= S_ * 32) return;
    int s = i / 32, p = i - (i / 32) * 32;
    // match reference: angle computed/rounded in fp32, trig evaluated accurately
    float f   = expf((float)(2 * p) * (-logf(10000.0f) / (float)HD_));
    float ang = (float)s * f;
    double a  = (double)ang;
    g_rope[i] = make_float2((float)cos(a), (float)sin(a));
}

__global__ void rope_apply_kernel() {
    int idx = blockIdx.x * blockDim.x + threadIdx.x;          // over B*S*H*32
    if (idx >= B_ * S_ * H_ * 32) return;
    int p = idx & 31;
    int h = (idx >> 5) % H_;
    int s = (idx / (32 * H_)) % S_;
    int b = idx / (32 * H_ * S_);
    float2 cs = g_rope[s * 32 + p];
    int base = ((b * S_ + s) * D_) + h * HD_ + 2 * p;
    float xr, xi;
    xr = g_q[base]; xi = g_q[base + 1];
    g_q[base]     = xr * cs.x - xi * cs.y;
    g_q[base + 1] = xr * cs.y + xi * cs.x;
    xr = g_k[base]; xi = g_k[base + 1];
    g_k[base]     = xr * cs.x - xi * cs.y;
    g_k[base + 1] = xr * cs.y + xi * cs.x;
}

// ---------------- attention: one block per (q-row, b*h) ----------------
__global__ __launch_bounds__(128)
void attn_kernel() {
    int sq = blockIdx.x;
    int bh = blockIdx.y;
    int b = bh / H_, h = bh - (bh / H_) * H_;
    int tid = threadIdx.x;
    __shared__ float qv[HD_];
    __shared__ float sc[S_];
    __shared__ float red[128];

    const float* qp = g_q + ((b * S_ + sq) * D_) + h * HD_;
    if (tid < HD_) qv[tid] = qp[tid];
    __syncthreads();

    for (int k = tid; k <= sq; k += 128) {
        const float4* kp = (const float4*)(g_k + ((b * S_ + k) * D_) + h * HD_);
        float d = 0.f;
#pragma unroll
        for (int j = 0; j < 16; j++) {
            float4 t = kp[j];
            d += qv[4 * j] * t.x + qv[4 * j + 1] * t.y + qv[4 * j + 2] * t.z + qv[4 * j + 3] * t.w;
        }
        sc[k] = d * 0.125f;     // 1/sqrt(64)
    }
    __syncthreads();

    float m = -1e30f;
    for (int k = tid; k <= sq; k += 128) m = fmaxf(m, sc[k]);
    red[tid] = m; __syncthreads();
    for (int st = 64; st > 0; st >>= 1) {
        if (tid < st) red[tid] = fmaxf(red[tid], red[tid + st]);
        __syncthreads();
    }
    m = red[0];
    __syncthreads();

    float ssum = 0.f;
    for (int k = tid; k <= sq; k += 128) { float p = expf(sc[k] - m); sc[k] = p; ssum += p; }
    red[tid] = ssum; __syncthreads();
    for (int st = 64; st > 0; st >>= 1) {
        if (tid < st) red[tid] += red[tid + st];
        __syncthreads();
    }
    float inv = 1.f / red[0];
    __syncthreads();

    int d = tid & 63, half = tid >> 6;
    float acc = 0.f;
    for (int k = half; k <= sq; k += 2)
        acc += sc[k] * g_v[((b * S_ + k) * D_) + h * HD_ + d];
    red[tid] = acc; __syncthreads();
    if (tid < HD_)
        g_o[((b * S_ + sq) * D_) + h * HD_ + tid] = (red[tid] + red[tid + 64]) * inv;
}

// ---------------- sum of softplus over c ----------------
__global__ void softplus_sum_kernel() {
    __shared__ float red[256];
    size_t n = (size_t)NT_ * V_;
    float ps = 0.f;
    for (size_t i = (size_t)blockIdx.x * blockDim.x + threadIdx.x; i < n;
         i += (size_t)gridDim.x * blockDim.x)
        ps += softplusf(g_c[i]);
    red[threadIdx.x] = ps; __syncthreads();
    for (int st = 128; st > 0; st >>= 1) {
        if (threadIdx.x < st) red[threadIdx.x] += red[threadIdx.x + st];
        __syncthreads();
    }
    if (threadIdx.x == 0) atomicAdd(&g_acc[0], (double)red[0]);
}

// ---------------- sparse BCE correction (targets & dup weights) ----------------
__global__ void corr_kernel(const int* __restrict__ y) {
    int s = blockIdx.x * blockDim.x + threadIdx.x;
    if (s >= S_) return;
    int tok[2][FCS_];
    for (int b = 0; b < 2; b++)
        for (int j = 0; j < FCS_; j++)
            tok[b][j] = y[b * YW_ + (FCS_ - 1) + ((s - (FCS_ - 1) + j + S_) & (S_ - 1))];
    double dsum = 0.0;
    for (int b = 0; b < 2; b++)
        for (int j = 0; j < FCS_; j++) {
            int v = tok[b][j];
            bool first = true;
            for (int b2 = 0; b2 <= b && first; b2++) {
                int jmax = (b2 == b) ? j : FCS_;
                for (int j2 = 0; j2 < jmax; j2++)
                    if (tok[b2][j2] == v) { first = false; break; }
            }
            if (!first) continue;
            int c0 = 0, c1 = 0;
            for (int j2 = 0; j2 < FCS_; j2++) {
                c0 += (tok[0][j2] == v);
                c1 += (tok[1][j2] == v);
            }
            float w = (c0 > 1 || c1 > 1) ? 1.5f : 1.0f;
            for (int b2 = 0; b2 < 2; b2++) {
                float cv = g_c[((size_t)(b2 * S_ + s)) * V_ + v];
                float t  = ((b2 == 0 ? c0 : c1) > 0) ? 1.f : 0.f;
                dsum += (double)((w - 1.f) * softplusf(cv) - w * t * cv);
            }
        }
    atomicAdd(&g_acc[1], dsum);
}

// ---------------- logits += causal exp-kernel conv of c ----------------
__global__ void ctx_add_kernel(float* __restrict__ logits, const float* __restrict__ conv_w) {
    __shared__ float sh_e;
    if (threadIdx.x == 0) sh_e = expf(-conv_w[0]);
    __syncthreads();
    size_t idx = (size_t)blockIdx.x * blockDim.x + threadIdx.x;
    if (idx >= (size_t)NT_ * V_) return;
    int v = (int)(idx % V_);
    int row = (int)(idx / V_);
    int s = row % S_, b = row / S_;
    float e = sh_e;
    float add = 0.f, w = 1.f;
    for (int d = FCS_; d >= 1; --d) {       // weight = e^(FCS_-d)
        int sp = s - d;
        if (sp >= 0) add += w * g_c[((size_t)(b * S_ + sp)) * V_ + v];
        w *= e;
    }
    logits[idx] += add;
}

// ---------------- NLL (log-softmax over V) ----------------
__global__ void nll_kernel(const float* __restrict__ logits, const int* __restrict__ y) {
    int row = blockIdx.x;
    int b = row / S_, s = row - (row / S_) * S_;
    const float* lp = logits + (size_t)row * V_;
    __shared__ float red[256];
    float m = -1e30f;
    for (int v = threadIdx.x; v < V_; v += 256) m = fmaxf(m, lp[v]);
    red[threadIdx.x] = m; __syncthreads();
    for (int st = 128; st > 0; st >>= 1) {
        if (threadIdx.x < st) red[threadIdx.x] = fmaxf(red[threadIdx.x], red[threadIdx.x + st]);
        __syncthreads();
    }
    m = red[0];
    __syncthreads();
    float ssum = 0.f;
    for (int v = threadIdx.x; v < V_; v += 256) ssum += expf(lp[v] - m);
    red[threadIdx.x] = ssum; __syncthreads();
    for (int st = 128; st > 0; st >>= 1) {
        if (threadIdx.x < st) red[threadIdx.x] += red[threadIdx.x + st];
        __syncthreads();
    }
    if (threadIdx.x == 0) {
        int yt = y[b * YW_ + s];
        if (yt != -1) {
            float lse = m + logf(red[0]);
            atomicAdd(&g_acc[2], (double)(lse - lp[yt]));
            atomicAdd(&g_acc[3], 1.0);
        }
    }
}

__global__ void finalize_kernel(float* __restrict__ out) {
    double cnt = g_acc[3] < 1.0 ? 1.0 : g_acc[3];
    out[(size_t)NT_ * V_]     = (float)(g_acc[2] / cnt);
    out[(size_t)NT_ * V_ + 1] = (float)((g_acc[0] + g_acc[1]) / ((double)NT_ * (double)V_));
}

// ---------------- launcher ----------------
extern "C" void kernel_launch(void* const* d_in, const int* in_sizes, int n_in,
                              void* d_out, int out_size) {
    const int*   x      = (const int*)  d_in[0];
    const int*   y      = (const int*)  d_in[1];
    const float* emb    = (const float*)d_in[2];
    const float* wq     = (const float*)d_in[3];
    const float* wk     = (const float*)d_in[4];
    const float* wv     = (const float*)d_in[5];
    const float* wo     = (const float*)d_in[6];
    const float* w1     = (const float*)d_in[7];
    const float* w2     = (const float*)d_in[8];
    const float* w3     = (const float*)d_in[9];
    const float* attn_n = (const float*)d_in[10];
    const float* ffn_n  = (const float*)d_in[11];
    const float* out_n  = (const float*)d_in[12];
    const float* w_out  = (const float*)d_in[13];
    const float* w_ctx  = (const float*)d_in[14];
    const float* conv_w = (const float*)d_in[15];
    float* out = (float*)d_out;

    float *h_, *a_, *q_, *k_, *v_, *o_, *g1_, *u1_, *c_;
    cudaGetSymbolAddress((void**)&h_,  g_h);
    cudaGetSymbolAddress((void**)&a_,  g_a);
    cudaGetSymbolAddress((void**)&q_,  g_q);
    cudaGetSymbolAddress((void**)&k_,  g_k);
    cudaGetSymbolAddress((void**)&v_,  g_v);
    cudaGetSymbolAddress((void**)&o_,  g_o);
    cudaGetSymbolAddress((void**)&g1_, g_g1);
    cudaGetSymbolAddress((void**)&u1_, g_u1);
    cudaGetSymbolAddress((void**)&c_,  g_c);

    zero_acc_kernel<<<1, 32>>>();
    embed_kernel<<<(NT_ * D_ + 255) / 256, 256>>>(x, emb);
    rope_table_kernel<<<(S_ * 32 + 255) / 256, 256>>>();

    dim3 gD(D_ / 64, NT_ / 64);   // 12 x 16
    dim3 gF(F_ / 64, NT_ / 64);   // 32 x 16
    dim3 gV(V_ / 64, NT_ / 64);   // 500 x 16

    for (int i = 0; i < L_; i++) {
        const float* wq_i = wq + (size_t)i * D_ * D_;
        const float* wk_i = wk + (size_t)i * D_ * D_;
        const float* wv_i = wv + (size_t)i * D_ * D_;
        const float* wo_i = wo + (size_t)i * D_ * D_;
        const float* w1_i = w1 + (size_t)i * F_ * D_;
        const float* w2_i = w2 + (size_t)i * D_ * F_;
        const float* w3_i = w3 + (size_t)i * F_ * D_;

        rmsnorm_kernel<<<NT_, 256>>>(h_, attn_n + i * D_, a_);
        gemm_nt<0><<<gD, 256>>>(a_, wq_i, q_, nullptr, NT_, D_, D_);
        gemm_nt<0><<<gD, 256>>>(a_, wk_i, k_, nullptr, NT_, D_, D_);
        gemm_nt<0><<<gD, 256>>>(a_, wv_i, v_, nullptr, NT_, D_, D_);
        rope_apply_kernel<<<(B_ * S_ * H_ * 32 + 255) / 256, 256>>>();
        attn_kernel<<<dim3(S_, B_ * H_), 128>>>();
        gemm_nt<1><<<gD, 256>>>(o_, wo_i, h_, nullptr, NT_, D_, D_);   // h += o @ wo^T

        rmsnorm_kernel<<<NT_, 256>>>(h_, ffn_n + i * D_, a_);
        gemm_nt<2><<<gF, 256>>>(a_, w1_i, g1_, nullptr, NT_, F_, D_);  // gate = silu(a@w1^T)
        gemm_nt<3><<<gF, 256>>>(a_, w3_i, u1_, g1_,     NT_, F_, D_);  // up = (a@w3^T)*gate
        gemm_nt<1><<<gD, 256>>>(u1_, w2_i, h_, nullptr, NT_, D_, F_);  // h += up @ w2^T
    }

    rmsnorm_kernel<<<NT_, 256>>>(h_, out_n, a_);
    gemm_nt<0><<<gV, 256>>>(a_, w_out, out, nullptr, NT_, V_, D_);     // logits
    gemm_nt<0><<<gV, 256>>>(a_, w_ctx, c_,  nullptr, NT_, V_, D_);     // c

    softplus_sum_kernel<<<2048, 256>>>();
    corr_kernel<<<(S_ + 255) / 256, 256>>>(y);
    ctx_add_kernel<<<(int)(((size_t)NT_ * V_ + 255) / 256), 256>>>(out, conv_w);
    nll_kernel<<<NT_, 256>>>(out, y);
    finalize_kernel<<<1, 1>>>(out);
}

// round 3
// speedup vs baseline: 1.1331x; 1.1331x over previous
#include <cuda_runtime.h>
#include <math.h>

#define B_  2
#define S_  512
#define V_  32000
#define D_  768
#define F_  2048
#define L_  4
#define H_  12
#define HD_ 64
#define FCS_ 8
#define YW_ (S_ + FCS_ - 1)   /* 519 */
#define NT_ (B_ * S_)         /* 1024 rows */

// ---------------- static scratch (allocation-free rule) ----------------
__device__ float  g_h [NT_ * D_];
__device__ float  g_a [NT_ * D_];
__device__ float  g_q [NT_ * D_];
__device__ float  g_k [NT_ * D_];
__device__ float  g_v [NT_ * D_];
__device__ float  g_o [NT_ * D_];
__device__ float  g_g1[NT_ * F_];
__device__ float  g_u1[NT_ * F_];
__device__ float  g_c [NT_ * V_];      // context head logits c (131 MB)
__device__ float2 g_rope[S_ * 32];
__device__ double g_acc[4];            // [0]=softplus_sum [1]=delta [2]=nll_sum [3]=valid

// ---------------- f32x2 packed helpers ----------------
typedef unsigned long long u64;

__device__ __forceinline__ u64 pk2(float lo, float hi) {
    u64 r; asm("mov.b64 %0, {%1, %2};" : "=l"(r) : "f"(lo), "f"(hi)); return r;
}
__device__ __forceinline__ void upk2(u64 v, float& lo, float& hi) {
    asm("mov.b64 {%0, %1}, %2;" : "=f"(lo), "=f"(hi) : "l"(v));
}
__device__ __forceinline__ u64 ffma2(u64 a, u64 b, u64 c) {
    u64 d; asm("fma.rn.f32x2 %0, %1, %2, %3;" : "=l"(d) : "l"(a), "l"(b), "l"(c)); return d;
}

__device__ __forceinline__ float softplusf(float x) {
    if (x > 15.0f) return x;
    return log1pf(expf(x));
}

__global__ void zero_acc_kernel() {
    if (threadIdx.x < 4) g_acc[threadIdx.x] = 0.0;
}

// ---------------- embedding gather ----------------
__global__ void embed_kernel(const int* __restrict__ x, const float* __restrict__ emb) {
    int i = blockIdx.x * blockDim.x + threadIdx.x;
    if (i >= NT_ * D_) return;
    int row = i / D_;
    int d   = i - row * D_;
    g_h[i] = emb[(size_t)x[row] * D_ + d];
}

// ---------------- rmsnorm ----------------
__global__ void rmsnorm_kernel(const float* __restrict__ in, const float* __restrict__ w,
                               float* __restrict__ out) {
    int row = blockIdx.x;
    const float* ip = in + row * D_;
    float* op = out + row * D_;
    __shared__ float red[256];
    float ss = 0.f;
    for (int d = threadIdx.x; d < D_; d += 256) { float v = ip[d]; ss += v * v; }
    red[threadIdx.x] = ss; __syncthreads();
    for (int st = 128; st > 0; st >>= 1) {
        if (threadIdx.x < st) red[threadIdx.x] += red[threadIdx.x + st];
        __syncthreads();
    }
    float rs = rsqrtf(red[0] / (float)D_ + 1e-5f);
    for (int d = threadIdx.x; d < D_; d += 256) op[d] = ip[d] * rs * w[d];
}

// =======================================================================
//  f32x2 NT-GEMM core:  C[m,n] (op)= sum_k A[m,k] * B[n,k]
//  BMxBN block tile, 256 threads, TMxTN per thread, accumulators packed
//  along m (pairs).  EPI: 0=store 1=add 2=silu 3=mulG 4=store+softplus-sum
// =======================================================================
template<int BM, int BN, int TM, int TN, int EPI>
__device__ __forceinline__ void gemm_core(const float* __restrict__ A,
                                          const float* __restrict__ Bw,
                                          float* __restrict__ C,
                                          const float* __restrict__ G,
                                          int N, int K) {
    constexpr int KT  = 16;
    constexpr int LDA = BM + 4;
    constexpr int LDB = BN + 4;
    __shared__ float As[KT][LDA];
    __shared__ float Bs[KT][LDB];
    __shared__ float sred[256];

    const int tid = threadIdx.x;
    constexpr int NTX = BN / TN;
    const int tx = tid % NTX;
    const int ty = tid / NTX;
    const int bm = blockIdx.y * BM;
    const int bn = blockIdx.x * BN;

    constexpr int NLA = (BM * KT) / (256 * 4);   // float4 per thread (A)
    constexpr int NLB = (BN * KT) / (256 * 4);
    const int lrA = tid % BM, ksA = (tid / BM) * (4 * NLA);
    const int lrB = tid % BN, ksB = (tid / BN) * (4 * NLB);
    const float* Aldg = A  + (size_t)(bm + lrA) * K + ksA;
    const float* Bldg = Bw + (size_t)(bn + lrB) * K + ksB;

    float4 pa[NLA], pb[NLB];
#pragma unroll
    for (int l = 0; l < NLA; l++) pa[l] = *(const float4*)(Aldg + 4 * l);
#pragma unroll
    for (int l = 0; l < NLB; l++) pb[l] = *(const float4*)(Bldg + 4 * l);
#pragma unroll
    for (int l = 0; l < NLA; l++) {
        As[ksA + 4*l + 0][lrA] = pa[l].x; As[ksA + 4*l + 1][lrA] = pa[l].y;
        As[ksA + 4*l + 2][lrA] = pa[l].z; As[ksA + 4*l + 3][lrA] = pa[l].w;
    }
#pragma unroll
    for (int l = 0; l < NLB; l++) {
        Bs[ksB + 4*l + 0][lrB] = pb[l].x; Bs[ksB + 4*l + 1][lrB] = pb[l].y;
        Bs[ksB + 4*l + 2][lrB] = pb[l].z; Bs[ksB + 4*l + 3][lrB] = pb[l].w;
    }
    __syncthreads();

    u64 acc[TM / 2][TN];
#pragma unroll
    for (int i = 0; i < TM / 2; i++)
#pragma unroll
        for (int j = 0; j < TN; j++) acc[i][j] = 0ull;

    const int nk = K / KT;
    for (int kt = 0; kt < nk; kt++) {
        if (kt + 1 < nk) {
            const float* Ap = Aldg + (kt + 1) * KT;
            const float* Bp = Bldg + (kt + 1) * KT;
#pragma unroll
            for (int l = 0; l < NLA; l++) pa[l] = *(const float4*)(Ap + 4 * l);
#pragma unroll
            for (int l = 0; l < NLB; l++) pb[l] = *(const float4*)(Bp + 4 * l);
        }
#pragma unroll
        for (int k = 0; k < KT; k++) {
            u64 a2[TM / 2];
#pragma unroll
            for (int q = 0; q < TM / 4; q++) {
                float4 t = *(const float4*)&As[k][ty * TM + 4 * q];
                a2[2 * q]     = pk2(t.x, t.y);
                a2[2 * q + 1] = pk2(t.z, t.w);
            }
#pragma unroll
            for (int q = 0; q < TN / 4; q++) {
                float4 t = *(const float4*)&Bs[k][tx * TN + 4 * q];
                u64 b0 = pk2(t.x, t.x), b1 = pk2(t.y, t.y);
                u64 b2 = pk2(t.z, t.z), b3 = pk2(t.w, t.w);
#pragma unroll
                for (int i = 0; i < TM / 2; i++) {
                    acc[i][4*q + 0] = ffma2(a2[i], b0, acc[i][4*q + 0]);
                    acc[i][4*q + 1] = ffma2(a2[i], b1, acc[i][4*q + 1]);
                    acc[i][4*q + 2] = ffma2(a2[i], b2, acc[i][4*q + 2]);
                    acc[i][4*q + 3] = ffma2(a2[i], b3, acc[i][4*q + 3]);
                }
            }
        }
        __syncthreads();
        if (kt + 1 < nk) {
#pragma unroll
            for (int l = 0; l < NLA; l++) {
                As[ksA + 4*l + 0][lrA] = pa[l].x; As[ksA + 4*l + 1][lrA] = pa[l].y;
                As[ksA + 4*l + 2][lrA] = pa[l].z; As[ksA + 4*l + 3][lrA] = pa[l].w;
            }
#pragma unroll
            for (int l = 0; l < NLB; l++) {
                Bs[ksB + 4*l + 0][lrB] = pb[l].x; Bs[ksB + 4*l + 1][lrB] = pb[l].y;
                Bs[ksB + 4*l + 2][lrB] = pb[l].z; Bs[ksB + 4*l + 3][lrB] = pb[l].w;
            }
            __syncthreads();
        }
    }

    // ---------------- epilogue ----------------
    float spsum = 0.f;
#pragma unroll
    for (int i = 0; i < TM; i++) {
        size_t idx = (size_t)(bm + ty * TM + i) * N + bn + tx * TN;
#pragma unroll
        for (int q = 0; q < TN / 4; q++) {
            float4 r;
            float lo, hi;
            upk2(acc[i >> 1][4*q + 0], lo, hi); r.x = (i & 1) ? hi : lo;
            upk2(acc[i >> 1][4*q + 1], lo, hi); r.y = (i & 1) ? hi : lo;
            upk2(acc[i >> 1][4*q + 2], lo, hi); r.z = (i & 1) ? hi : lo;
            upk2(acc[i >> 1][4*q + 3], lo, hi); r.w = (i & 1) ? hi : lo;
            if (EPI == 1) {
                float4 o = *(const float4*)(C + idx + 4 * q);
                r.x += o.x; r.y += o.y; r.z += o.z; r.w += o.w;
            } else if (EPI == 2) {
                r.x = r.x / (1.f + expf(-r.x));
                r.y = r.y / (1.f + expf(-r.y));
                r.z = r.z / (1.f + expf(-r.z));
                r.w = r.w / (1.f + expf(-r.w));
            } else if (EPI == 3) {
                float4 gg = *(const float4*)(G + idx + 4 * q);
                r.x *= gg.x; r.y *= gg.y; r.z *= gg.z; r.w *= gg.w;
            } else if (EPI == 4) {
                spsum += softplusf(r.x) + softplusf(r.y) + softplusf(r.z) + softplusf(r.w);
            }
            *(float4*)(C + idx + 4 * q) = r;
        }
    }
    if (EPI == 4) {
        sred[tid] = spsum; __syncthreads();
        for (int st = 128; st > 0; st >>= 1) {
            if (tid < st) sred[tid] += sred[tid + st];
            __syncthreads();
        }
        if (tid == 0) atomicAdd(&g_acc[0], (double)sred[0]);
    }
}

template<int BM, int BN, int TM, int TN, int EPI, int OCC>
__global__ __launch_bounds__(256, OCC)
void gemm_k(const float* __restrict__ A, const float* __restrict__ Bw,
            float* __restrict__ C, const float* __restrict__ G, int N, int K) {
    gemm_core<BM, BN, TM, TN, EPI>(A, Bw, C, G, N, K);
}

// fused q/k/v: blockIdx.z selects weight + output
__global__ __launch_bounds__(256, 3)
void gemm_qkv(const float* __restrict__ A,
              const float* __restrict__ B0, const float* __restrict__ B1,
              const float* __restrict__ B2,
              float* __restrict__ C0, float* __restrict__ C1, float* __restrict__ C2,
              int N, int K) {
    const float* Bz = (blockIdx.z == 0) ? B0 : (blockIdx.z == 1) ? B1 : B2;
    float*       Cz = (blockIdx.z == 0) ? C0 : (blockIdx.z == 1) ? C1 : C2;
    gemm_core<64, 64, 4, 4, 0>(A, Bz, Cz, nullptr, N, K);
}

// ---------------- RoPE ----------------
__global__ void rope_table_kernel() {
    int i = blockIdx.x * blockDim.x + threadIdx.x;
    if (i >= S_ * 32) return;
    int s = i / 32, p = i - (i / 32) * 32;
    float f   = expf((float)(2 * p) * (-logf(10000.0f) / (float)HD_));
    float ang = (float)s * f;
    double a  = (double)ang;
    g_rope[i] = make_float2((float)cos(a), (float)sin(a));
}

__global__ void rope_apply_kernel() {
    int idx = blockIdx.x * blockDim.x + threadIdx.x;          // over B*S*H*32
    if (idx >= B_ * S_ * H_ * 32) return;
    int p = idx & 31;
    int h = (idx >> 5) % H_;
    int s = (idx / (32 * H_)) % S_;
    int b = idx / (32 * H_ * S_);
    float2 cs = g_rope[s * 32 + p];
    int base = ((b * S_ + s) * D_) + h * HD_ + 2 * p;
    float xr, xi;
    xr = g_q[base]; xi = g_q[base + 1];
    g_q[base]     = xr * cs.x - xi * cs.y;
    g_q[base + 1] = xr * cs.y + xi * cs.x;
    xr = g_k[base]; xi = g_k[base + 1];
    g_k[base]     = xr * cs.x - xi * cs.y;
    g_k[base + 1] = xr * cs.y + xi * cs.x;
}

// ---------------- attention ----------------
__global__ __launch_bounds__(128)
void attn_kernel() {
    int sq = blockIdx.x;
    int bh = blockIdx.y;
    int b = bh / H_, h = bh - (bh / H_) * H_;
    int tid = threadIdx.x;
    __shared__ float qv[HD_];
    __shared__ float sc[S_];
    __shared__ float red[128];

    const float* qp = g_q + ((b * S_ + sq) * D_) + h * HD_;
    if (tid < HD_) qv[tid] = qp[tid];
    __syncthreads();

    for (int k = tid; k <= sq; k += 128) {
        const float4* kp = (const float4*)(g_k + ((b * S_ + k) * D_) + h * HD_);
        float d = 0.f;
#pragma unroll
        for (int j = 0; j < 16; j++) {
            float4 t = kp[j];
            d += qv[4 * j] * t.x + qv[4 * j + 1] * t.y + qv[4 * j + 2] * t.z + qv[4 * j + 3] * t.w;
        }
        sc[k] = d * 0.125f;
    }
    __syncthreads();

    float m = -1e30f;
    for (int k = tid; k <= sq; k += 128) m = fmaxf(m, sc[k]);
    red[tid] = m; __syncthreads();
    for (int st = 64; st > 0; st >>= 1) {
        if (tid < st) red[tid] = fmaxf(red[tid], red[tid + st]);
        __syncthreads();
    }
    m = red[0];
    __syncthreads();

    float ssum = 0.f;
    for (int k = tid; k <= sq; k += 128) { float p = expf(sc[k] - m); sc[k] = p; ssum += p; }
    red[tid] = ssum; __syncthreads();
    for (int st = 64; st > 0; st >>= 1) {
        if (tid < st) red[tid] += red[tid + st];
        __syncthreads();
    }
    float inv = 1.f / red[0];
    __syncthreads();

    int d = tid & 63, half = tid >> 6;
    float acc = 0.f;
    for (int k = half; k <= sq; k += 2)
        acc += sc[k] * g_v[((b * S_ + k) * D_) + h * HD_ + d];
    red[tid] = acc; __syncthreads();
    if (tid < HD_)
        g_o[((b * S_ + sq) * D_) + h * HD_ + tid] = (red[tid] + red[tid + 64]) * inv;
}

// ---------------- sparse BCE correction ----------------
__global__ void corr_kernel(const int* __restrict__ y) {
    int s = blockIdx.x * blockDim.x + threadIdx.x;
    if (s >= S_) return;
    int tok[2][FCS_];
    for (int b = 0; b < 2; b++)
        for (int j = 0; j < FCS_; j++)
            tok[b][j] = y[b * YW_ + (FCS_ - 1) + ((s - (FCS_ - 1) + j + S_) & (S_ - 1))];
    double dsum = 0.0;
    for (int b = 0; b < 2; b++)
        for (int j = 0; j < FCS_; j++) {
            int v = tok[b][j];
            bool first = true;
            for (int b2 = 0; b2 <= b && first; b2++) {
                int jmax = (b2 == b) ? j : FCS_;
                for (int j2 = 0; j2 < jmax; j2++)
                    if (tok[b2][j2] == v) { first = false; break; }
            }
            if (!first) continue;
            int c0 = 0, c1 = 0;
            for (int j2 = 0; j2 < FCS_; j2++) {
                c0 += (tok[0][j2] == v);
                c1 += (tok[1][j2] == v);
            }
            float w = (c0 > 1 || c1 > 1) ? 1.5f : 1.0f;
            for (int b2 = 0; b2 < 2; b2++) {
                float cv = g_c[((size_t)(b2 * S_ + s)) * V_ + v];
                float t  = ((b2 == 0 ? c0 : c1) > 0) ? 1.f : 0.f;
                dsum += (double)((w - 1.f) * softplusf(cv) - w * t * cv);
            }
        }
    atomicAdd(&g_acc[1], dsum);
}

// ---------------- logits += exp-kernel context (ring-buffer window) ----
// context[s] = sum_{d=1..8} e^(8-d) * c[s-d],  e = exp(-conv_w[0])
#define CTX_CHUNK 128
__global__ void ctx_scan_kernel(float* __restrict__ logits, const float* __restrict__ conv_w) {
    int v = blockIdx.x * blockDim.x + threadIdx.x;
    if (v >= V_) return;
    int b  = blockIdx.y;
    int s0 = blockIdx.z * CTX_CHUNK;     // multiple of 8
    float e = expf(-conv_w[0]);

    // pw[d-1] = e^(8-d): weight for lag d
    float pw[FCS_];
    pw[FCS_ - 1] = 1.f;
#pragma unroll
    for (int d = FCS_ - 1; d >= 1; --d) pw[d - 1] = pw[d] * e;

    // ring[s & 7] holds c[s]; prefill with c[s0-8 .. s0-1] (0 if s<0)
    float ring[FCS_];
#pragma unroll
    for (int j = 1; j <= FCS_; j++) {
        int sp = s0 - j;
        ring[(8 - j) & 7] = (sp >= 0) ? g_c[((size_t)(b * S_ + sp)) * V_ + v] : 0.f;
    }

    for (int t = 0; t < CTX_CHUNK / 8; t++) {
#pragma unroll
        for (int u = 0; u < 8; u++) {
            int s = s0 + 8 * t + u;
            size_t idx = ((size_t)(b * S_ + s)) * V_ + v;
            float ctx = 0.f;
#pragma unroll
            for (int d = 1; d <= FCS_; d++)
                ctx += pw[d - 1] * ring[(u - d) & 7];
            logits[idx] += ctx;
            ring[u] = g_c[idx];           // c[s] enters the window
        }
    }
}

// ---------------- NLL ----------------
__global__ void nll_kernel(const float* __restrict__ logits, const int* __restrict__ y) {
    int row = blockIdx.x;
    int b = row / S_, s = row - (row / S_) * S_;
    const float* lp = logits + (size_t)row * V_;
    __shared__ float red[256];
    float m = -1e30f;
    for (int v = threadIdx.x; v < V_; v += 256) m = fmaxf(m, lp[v]);
    red[threadIdx.x] = m; __syncthreads();
    for (int st = 128; st > 0; st >>= 1) {
        if (threadIdx.x < st) red[threadIdx.x] = fmaxf(red[threadIdx.x], red[threadIdx.x + st]);
        __syncthreads();
    }
    m = red[0];
    __syncthreads();
    float ssum = 0.f;
    for (int v = threadIdx.x; v < V_; v += 256) ssum += expf(lp[v] - m);
    red[threadIdx.x] = ssum; __syncthreads();
    for (int st = 128; st > 0; st >>= 1) {
        if (threadIdx.x < st) red[threadIdx.x] += red[threadIdx.x + st];
        __syncthreads();
    }
    if (threadIdx.x == 0) {
        int yt = y[b * YW_ + s];
        if (yt != -1) {
            float lse = m + logf(red[0]);
            atomicAdd(&g_acc[2], (double)(lse - lp[yt]));
            atomicAdd(&g_acc[3], 1.0);
        }
    }
}

__global__ void finalize_kernel(float* __restrict__ out) {
    double cnt = g_acc[3] < 1.0 ? 1.0 : g_acc[3];
    out[(size_t)NT_ * V_]     = (float)(g_acc[2] / cnt);
    out[(size_t)NT_ * V_ + 1] = (float)((g_acc[0] + g_acc[1]) / ((double)NT_ * (double)V_));
}

// ---------------- launcher ----------------
extern "C" void kernel_launch(void* const* d_in, const int* in_sizes, int n_in,
                              void* d_out, int out_size) {
    const int*   x      = (const int*)  d_in[0];
    const int*   y      = (const int*)  d_in[1];
    const float* emb    = (const float*)d_in[2];
    const float* wq     = (const float*)d_in[3];
    const float* wk     = (const float*)d_in[4];
    const float* wv     = (const float*)d_in[5];
    const float* wo     = (const float*)d_in[6];
    const float* w1     = (const float*)d_in[7];
    const float* w2     = (const float*)d_in[8];
    const float* w3     = (const float*)d_in[9];
    const float* attn_n = (const float*)d_in[10];
    const float* ffn_n  = (const float*)d_in[11];
    const float* out_n  = (const float*)d_in[12];
    const float* w_out  = (const float*)d_in[13];
    const float* w_ctx  = (const float*)d_in[14];
    const float* conv_w = (const float*)d_in[15];
    float* out = (float*)d_out;

    float *h_, *a_, *q_, *k_, *v_, *o_, *g1_, *u1_, *c_;
    cudaGetSymbolAddress((void**)&h_,  g_h);
    cudaGetSymbolAddress((void**)&a_,  g_a);
    cudaGetSymbolAddress((void**)&q_,  g_q);
    cudaGetSymbolAddress((void**)&k_,  g_k);
    cudaGetSymbolAddress((void**)&v_,  g_v);
    cudaGetSymbolAddress((void**)&o_,  g_o);
    cudaGetSymbolAddress((void**)&g1_, g_g1);
    cudaGetSymbolAddress((void**)&u1_, g_u1);
    cudaGetSymbolAddress((void**)&c_,  g_c);

    zero_acc_kernel<<<1, 32>>>();
    embed_kernel<<<(NT_ * D_ + 255) / 256, 256>>>(x, emb);
    rope_table_kernel<<<(S_ * 32 + 255) / 256, 256>>>();

    dim3 gQKV(D_ / 64, NT_ / 64, 3);     // 12 x 16 x 3
    dim3 gDs(D_ / 64, NT_ / 64);         // 12 x 16
    dim3 gF(F_ / 64, NT_ / 128);         // 32 x 8  (128x64 tiles)
    dim3 gV(V_ / 128, NT_ / 128);        // 250 x 8 (128x128 tiles)

    for (int i = 0; i < L_; i++) {
        const float* wq_i = wq + (size_t)i * D_ * D_;
        const float* wk_i = wk + (size_t)i * D_ * D_;
        const float* wv_i = wv + (size_t)i * D_ * D_;
        const float* wo_i = wo + (size_t)i * D_ * D_;
        const float* w1_i = w1 + (size_t)i * F_ * D_;
        const float* w2_i = w2 + (size_t)i * D_ * F_;
        const float* w3_i = w3 + (size_t)i * F_ * D_;

        rmsnorm_kernel<<<NT_, 256>>>(h_, attn_n + i * D_, a_);
        gemm_qkv<<<gQKV, 256>>>(a_, wq_i, wk_i, wv_i, q_, k_, v_, D_, D_);
        rope_apply_kernel<<<(B_ * S_ * H_ * 32 + 255) / 256, 256>>>();
        attn_kernel<<<dim3(S_, B_ * H_), 128>>>();
        gemm_k<64, 64, 4, 4, 1, 3><<<gDs, 256>>>(o_, wo_i, h_, nullptr, D_, D_);

        rmsnorm_kernel<<<NT_, 256>>>(h_, ffn_n + i * D_, a_);
        gemm_k<128, 64, 8, 4, 2, 2><<<gF, 256>>>(a_, w1_i, g1_, nullptr, F_, D_);
        gemm_k<128, 64, 8, 4, 3, 2><<<gF, 256>>>(a_, w3_i, u1_, g1_, F_, D_);
        gemm_k<64, 64, 4, 4, 1, 3><<<gDs, 256>>>(u1_, w2_i, h_, nullptr, D_, F_);
    }

    rmsnorm_kernel<<<NT_, 256>>>(h_, out_n, a_);
    gemm_k<128, 128, 8, 8, 0, 2><<<gV, 256>>>(a_, w_out, out, nullptr, V_, D_);  // logits
    gemm_k<128, 128, 8, 8, 4, 2><<<gV, 256>>>(a_, w_ctx, c_,  nullptr, V_, D_);  // c + softplus sum

    corr_kernel<<<(S_ + 255) / 256, 256>>>(y);
    ctx_scan_kernel<<<dim3((V_ + 255) / 256, B_, S_ / CTX_CHUNK), 256>>>(out, conv_w);
    nll_kernel<<<NT_, 256>>>(out, y);
    finalize_kernel<<<1, 1>>>(out);
}

// round 4
// speedup vs baseline: 1.4933x; 1.3178x over previous
#include <cuda_runtime.h>
#include <math.h>
#include <stdint.h>

#define B_  2
#define S_  512
#define V_  32000
#define D_  768
#define F_  2048
#define L_  4
#define H_  12
#define HD_ 64
#define FCS_ 8
#define YW_ (S_ + FCS_ - 1)   /* 519 */
#define NT_ (B_ * S_)         /* 1024 rows */

// ---------------- static scratch (allocation-free rule) ----------------
__device__ float  g_h [NT_ * D_];
__device__ float  g_a [NT_ * D_];
__device__ float  g_q [NT_ * D_];
__device__ float  g_k [NT_ * D_];
__device__ float  g_v [NT_ * D_];
__device__ float  g_o [NT_ * D_];
__device__ float  g_g1[NT_ * F_];
__device__ float  g_u1[NT_ * F_];
__device__ float  g_c [NT_ * V_];      // context head logits c (131 MB)
__device__ float2 g_rope[S_ * 32];
__device__ double g_acc[4];            // [0]=softplus_sum [1]=delta [2]=nll_sum [3]=valid

// ---------------- f32x2 packed helpers ----------------
typedef unsigned long long u64;

__device__ __forceinline__ u64 pk2(float lo, float hi) {
    u64 r; asm("mov.b64 %0, {%1, %2};" : "=l"(r) : "f"(lo), "f"(hi)); return r;
}
__device__ __forceinline__ void upk2(u64 v, float& lo, float& hi) {
    asm("mov.b64 {%0, %1}, %2;" : "=f"(lo), "=f"(hi) : "l"(v));
}
__device__ __forceinline__ u64 ffma2(u64 a, u64 b, u64 c) {
    u64 d; asm("fma.rn.f32x2 %0, %1, %2, %3;" : "=l"(d) : "l"(a), "l"(b), "l"(c)); return d;
}

__device__ __forceinline__ float softplusf(float x) {
    if (x > 15.0f) return x;
    return log1pf(expf(x));
}

__device__ __forceinline__ uint32_t f2tf32(float x) {
    uint32_t r; asm("cvt.rna.tf32.f32 %0, %1;" : "=r"(r) : "f"(x)); return r;
}

__device__ __forceinline__ void mma_tf32(float& c0, float& c1, float& c2, float& c3,
                                         uint32_t a0, uint32_t a1, uint32_t a2, uint32_t a3,
                                         uint32_t b0, uint32_t b1) {
    asm volatile("mma.sync.aligned.m16n8k8.row.col.f32.tf32.tf32.f32 "
                 "{%0,%1,%2,%3}, {%4,%5,%6,%7}, {%8,%9}, {%0,%1,%2,%3};"
                 : "+f"(c0), "+f"(c1), "+f"(c2), "+f"(c3)
                 : "r"(a0), "r"(a1), "r"(a2), "r"(a3), "r"(b0), "r"(b1));
}

__global__ void zero_acc_kernel() {
    if (threadIdx.x < 4) g_acc[threadIdx.x] = 0.0;
}

// ---------------- embedding gather ----------------
__global__ void embed_kernel(const int* __restrict__ x, const float* __restrict__ emb) {
    int i = blockIdx.x * blockDim.x + threadIdx.x;
    if (i >= NT_ * D_) return;
    int row = i / D_;
    int d   = i - row * D_;
    g_h[i] = emb[(size_t)x[row] * D_ + d];
}

// ---------------- rmsnorm ----------------
__global__ void rmsnorm_kernel(const float* __restrict__ in, const float* __restrict__ w,
                               float* __restrict__ out) {
    int row = blockIdx.x;
    const float* ip = in + row * D_;
    float* op = out + row * D_;
    __shared__ float red[256];
    float ss = 0.f;
    for (int d = threadIdx.x; d < D_; d += 256) { float v = ip[d]; ss += v * v; }
    red[threadIdx.x] = ss; __syncthreads();
    for (int st = 128; st > 0; st >>= 1) {
        if (threadIdx.x < st) red[threadIdx.x] += red[threadIdx.x + st];
        __syncthreads();
    }
    float rs = rsqrtf(red[0] / (float)D_ + 1e-5f);
    for (int d = threadIdx.x; d < D_; d += 256) op[d] = ip[d] * rs * w[d];
}

// =======================================================================
//  tf32 tensor-core NT-GEMM for the V-head projections.
//  C[m,n] = sum_k A[m,k]*W[n,k].  128x128 tile, 256 threads (2x4 warps,
//  64x32 warp tile), KT=16, fragments via m16n8k8 tf32 mma.
//  DOSP=1: also accumulate softplus(C) into g_acc[0].
// =======================================================================
#define TKT 16
#define TLD (TKT + 4)   /* smem row stride = 20 (conflict-free for frag loads) */

template<int DOSP>
__global__ __launch_bounds__(256, 2)
void gemm_tf32(const float* __restrict__ A, const float* __restrict__ Bw,
               float* __restrict__ C, int N, int K) {
    __shared__ uint32_t As[128][TLD];
    __shared__ uint32_t Bs[128][TLD];
    __shared__ float sred[256];

    const int tid  = threadIdx.x;
    const int lane = tid & 31;
    const int wid  = tid >> 5;
    const int wm   = wid >> 2;          // 0..1
    const int wn   = wid & 3;           // 0..3
    const int bm   = blockIdx.x * 128;  // m fast => weight-tile sharing in L2
    const int bn   = blockIdx.y * 128;

    const int lr = tid >> 1;            // 0..127
    const int ks = (tid & 1) * 8;       // 0 or 8
    const float* Ag = A  + (size_t)(bm + lr) * K + ks;
    const float* Bg = Bw + (size_t)(bn + lr) * K + ks;

    float acc[16][4];
#pragma unroll
    for (int i = 0; i < 16; i++)
#pragma unroll
        for (int j = 0; j < 4; j++) acc[i][j] = 0.f;

    float4 pa0 = *(const float4*)(Ag);
    float4 pa1 = *(const float4*)(Ag + 4);
    float4 pb0 = *(const float4*)(Bg);
    float4 pb1 = *(const float4*)(Bg + 4);

    const int nk = K / TKT;             // 48
    for (int kc = 0; kc < nk; kc++) {
        As[lr][ks + 0] = f2tf32(pa0.x); As[lr][ks + 1] = f2tf32(pa0.y);
        As[lr][ks + 2] = f2tf32(pa0.z); As[lr][ks + 3] = f2tf32(pa0.w);
        As[lr][ks + 4] = f2tf32(pa1.x); As[lr][ks + 5] = f2tf32(pa1.y);
        As[lr][ks + 6] = f2tf32(pa1.z); As[lr][ks + 7] = f2tf32(pa1.w);
        Bs[lr][ks + 0] = f2tf32(pb0.x); Bs[lr][ks + 1] = f2tf32(pb0.y);
        Bs[lr][ks + 2] = f2tf32(pb0.z); Bs[lr][ks + 3] = f2tf32(pb0.w);
        Bs[lr][ks + 4] = f2tf32(pb1.x); Bs[lr][ks + 5] = f2tf32(pb1.y);
        Bs[lr][ks + 6] = f2tf32(pb1.z); Bs[lr][ks + 7] = f2tf32(pb1.w);
        __syncthreads();

        if (kc + 1 < nk) {
            const float* Ap = Ag + (kc + 1) * TKT;
            const float* Bp = Bg + (kc + 1) * TKT;
            pa0 = *(const float4*)(Ap);
            pa1 = *(const float4*)(Ap + 4);
            pb0 = *(const float4*)(Bp);
            pb1 = *(const float4*)(Bp + 4);
        }

#pragma unroll
        for (int kk = 0; kk < 2; kk++) {
            const int kb = kk * 8;
            const int kq = kb + (lane & 3);
            uint32_t af[4][4], bf[4][2];
#pragma unroll
            for (int mt = 0; mt < 4; mt++) {
                int row = wm * 64 + mt * 16 + (lane >> 2);
                af[mt][0] = As[row][kq];
                af[mt][1] = As[row + 8][kq];
                af[mt][2] = As[row][kq + 4];
                af[mt][3] = As[row + 8][kq + 4];
            }
#pragma unroll
            for (int nt = 0; nt < 4; nt++) {
                int nr = wn * 32 + nt * 8 + (lane >> 2);
                bf[nt][0] = Bs[nr][kq];
                bf[nt][1] = Bs[nr][kq + 4];
            }
#pragma unroll
            for (int mt = 0; mt < 4; mt++)
#pragma unroll
                for (int nt = 0; nt < 4; nt++)
                    mma_tf32(acc[mt * 4 + nt][0], acc[mt * 4 + nt][1],
                             acc[mt * 4 + nt][2], acc[mt * 4 + nt][3],
                             af[mt][0], af[mt][1], af[mt][2], af[mt][3],
                             bf[nt][0], bf[nt][1]);
        }
        __syncthreads();
    }

    // ---------------- epilogue ----------------
    float spsum = 0.f;
#pragma unroll
    for (int mt = 0; mt < 4; mt++) {
        int r0 = bm + wm * 64 + mt * 16 + (lane >> 2);
#pragma unroll
        for (int nt = 0; nt < 4; nt++) {
            int cc = bn + wn * 32 + nt * 8 + (lane & 3) * 2;
            float* a4 = acc[mt * 4 + nt];
            *(float2*)(C + (size_t)r0 * N + cc)       = make_float2(a4[0], a4[1]);
            *(float2*)(C + (size_t)(r0 + 8) * N + cc) = make_float2(a4[2], a4[3]);
            if (DOSP)
                spsum += softplusf(a4[0]) + softplusf(a4[1]) +
                         softplusf(a4[2]) + softplusf(a4[3]);
        }
    }
    if (DOSP) {
        sred[tid] = spsum; __syncthreads();
        for (int st = 128; st > 0; st >>= 1) {
            if (tid < st) sred[tid] += sred[tid + st];
            __syncthreads();
        }
        if (tid == 0) atomicAdd(&g_acc[0], (double)sred[0]);
    }
}

// =======================================================================
//  f32x2 NT-GEMM (in-layer projections, verified fp32 path)
//  EPI: 0=store 1=add 2=silu 3=mulG
// =======================================================================
template<int BM, int BN, int TM, int TN, int EPI>
__device__ __forceinline__ void gemm_core(const float* __restrict__ A,
                                          const float* __restrict__ Bw,
                                          float* __restrict__ C,
                                          const float* __restrict__ G,
                                          int N, int K) {
    constexpr int KT  = 16;
    constexpr int LDA = BM + 4;
    constexpr int LDB = BN + 4;
    __shared__ float As[KT][LDA];
    __shared__ float Bs[KT][LDB];

    const int tid = threadIdx.x;
    constexpr int NTX = BN / TN;
    const int tx = tid % NTX;
    const int ty = tid / NTX;
    const int bm = blockIdx.y * BM;
    const int bn = blockIdx.x * BN;

    constexpr int NLA = (BM * KT) / (256 * 4);
    constexpr int NLB = (BN * KT) / (256 * 4);
    const int lrA = tid % BM, ksA = (tid / BM) * (4 * NLA);
    const int lrB = tid % BN, ksB = (tid / BN) * (4 * NLB);
    const float* Aldg = A  + (size_t)(bm + lrA) * K + ksA;
    const float* Bldg = Bw + (size_t)(bn + lrB) * K + ksB;

    float4 pa[NLA], pb[NLB];
#pragma unroll
    for (int l = 0; l < NLA; l++) pa[l] = *(const float4*)(Aldg + 4 * l);
#pragma unroll
    for (int l = 0; l < NLB; l++) pb[l] = *(const float4*)(Bldg + 4 * l);
#pragma unroll
    for (int l = 0; l < NLA; l++) {
        As[ksA + 4*l + 0][lrA] = pa[l].x; As[ksA + 4*l + 1][lrA] = pa[l].y;
        As[ksA + 4*l + 2][lrA] = pa[l].z; As[ksA + 4*l + 3][lrA] = pa[l].w;
    }
#pragma unroll
    for (int l = 0; l < NLB; l++) {
        Bs[ksB + 4*l + 0][lrB] = pb[l].x; Bs[ksB + 4*l + 1][lrB] = pb[l].y;
        Bs[ksB + 4*l + 2][lrB] = pb[l].z; Bs[ksB + 4*l + 3][lrB] = pb[l].w;
    }
    __syncthreads();

    u64 acc[TM / 2][TN];
#pragma unroll
    for (int i = 0; i < TM / 2; i++)
#pragma unroll
        for (int j = 0; j < TN; j++) acc[i][j] = 0ull;

    const int nk = K / KT;
    for (int kt = 0; kt < nk; kt++) {
        if (kt + 1 < nk) {
            const float* Ap = Aldg + (kt + 1) * KT;
            const float* Bp = Bldg + (kt + 1) * KT;
#pragma unroll
            for (int l = 0; l < NLA; l++) pa[l] = *(const float4*)(Ap + 4 * l);
#pragma unroll
            for (int l = 0; l < NLB; l++) pb[l] = *(const float4*)(Bp + 4 * l);
        }
#pragma unroll
        for (int k = 0; k < KT; k++) {
            u64 a2[TM / 2];
#pragma unroll
            for (int q = 0; q < TM / 4; q++) {
                float4 t = *(const float4*)&As[k][ty * TM + 4 * q];
                a2[2 * q]     = pk2(t.x, t.y);
                a2[2 * q + 1] = pk2(t.z, t.w);
            }
#pragma unroll
            for (int q = 0; q < TN / 4; q++) {
                float4 t = *(const float4*)&Bs[k][tx * TN + 4 * q];
                u64 b0 = pk2(t.x, t.x), b1 = pk2(t.y, t.y);
                u64 b2 = pk2(t.z, t.z), b3 = pk2(t.w, t.w);
#pragma unroll
                for (int i = 0; i < TM / 2; i++) {
                    acc[i][4*q + 0] = ffma2(a2[i], b0, acc[i][4*q + 0]);
                    acc[i][4*q + 1] = ffma2(a2[i], b1, acc[i][4*q + 1]);
                    acc[i][4*q + 2] = ffma2(a2[i], b2, acc[i][4*q + 2]);
                    acc[i][4*q + 3] = ffma2(a2[i], b3, acc[i][4*q + 3]);
                }
            }
        }
        __syncthreads();
        if (kt + 1 < nk) {
#pragma unroll
            for (int l = 0; l < NLA; l++) {
                As[ksA + 4*l + 0][lrA] = pa[l].x; As[ksA + 4*l + 1][lrA] = pa[l].y;
                As[ksA + 4*l + 2][lrA] = pa[l].z; As[ksA + 4*l + 3][lrA] = pa[l].w;
            }
#pragma unroll
            for (int l = 0; l < NLB; l++) {
                Bs[ksB + 4*l + 0][lrB] = pb[l].x; Bs[ksB + 4*l + 1][lrB] = pb[l].y;
                Bs[ksB + 4*l + 2][lrB] = pb[l].z; Bs[ksB + 4*l + 3][lrB] = pb[l].w;
            }
            __syncthreads();
        }
    }

    float spdummy = 0.f; (void)spdummy;
#pragma unroll
    for (int i = 0; i < TM; i++) {
        size_t idx = (size_t)(bm + ty * TM + i) * N + bn + tx * TN;
#pragma unroll
        for (int q = 0; q < TN / 4; q++) {
            float4 r;
            float lo, hi;
            upk2(acc[i >> 1][4*q + 0], lo, hi); r.x = (i & 1) ? hi : lo;
            upk2(acc[i >> 1][4*q + 1], lo, hi); r.y = (i & 1) ? hi : lo;
            upk2(acc[i >> 1][4*q + 2], lo, hi); r.z = (i & 1) ? hi : lo;
            upk2(acc[i >> 1][4*q + 3], lo, hi); r.w = (i & 1) ? hi : lo;
            if (EPI == 1) {
                float4 o = *(const float4*)(C + idx + 4 * q);
                r.x += o.x; r.y += o.y; r.z += o.z; r.w += o.w;
            } else if (EPI == 2) {
                r.x = r.x / (1.f + expf(-r.x));
                r.y = r.y / (1.f + expf(-r.y));
                r.z = r.z / (1.f + expf(-r.z));
                r.w = r.w / (1.f + expf(-r.w));
            } else if (EPI == 3) {
                float4 gg = *(const float4*)(G + idx + 4 * q);
                r.x *= gg.x; r.y *= gg.y; r.z *= gg.z; r.w *= gg.w;
            }
            *(float4*)(C + idx + 4 * q) = r;
        }
    }
}

template<int BM, int BN, int TM, int TN, int EPI, int OCC>
__global__ __launch_bounds__(256, OCC)
void gemm_k(const float* __restrict__ A, const float* __restrict__ Bw,
            float* __restrict__ C, const float* __restrict__ G, int N, int K) {
    gemm_core<BM, BN, TM, TN, EPI>(A, Bw, C, G, N, K);
}

// fused q/k/v: blockIdx.z selects weight + output
__global__ __launch_bounds__(256, 3)
void gemm_qkv(const float* __restrict__ A,
              const float* __restrict__ B0, const float* __restrict__ B1,
              const float* __restrict__ B2,
              float* __restrict__ C0, float* __restrict__ C1, float* __restrict__ C2,
              int N, int K) {
    const float* Bz = (blockIdx.z == 0) ? B0 : (blockIdx.z == 1) ? B1 : B2;
    float*       Cz = (blockIdx.z == 0) ? C0 : (blockIdx.z == 1) ? C1 : C2;
    gemm_core<64, 64, 4, 4, 0>(A, Bz, Cz, nullptr, N, K);
}

// ---------------- RoPE ----------------
__global__ void rope_table_kernel() {
    int i = blockIdx.x * blockDim.x + threadIdx.x;
    if (i >= S_ * 32) return;
    int s = i / 32, p = i - (i / 32) * 32;
    float f   = expf((float)(2 * p) * (-logf(10000.0f) / (float)HD_));
    float ang = (float)s * f;
    double a  = (double)ang;
    g_rope[i] = make_float2((float)cos(a), (float)sin(a));
}

__global__ void rope_apply_kernel() {
    int idx = blockIdx.x * blockDim.x + threadIdx.x;          // over B*S*H*32
    if (idx >= B_ * S_ * H_ * 32) return;
    int p = idx & 31;
    int h = (idx >> 5) % H_;
    int s = (idx / (32 * H_)) % S_;
    int b = idx / (32 * H_ * S_);
    float2 cs = g_rope[s * 32 + p];
    int base = ((b * S_ + s) * D_) + h * HD_ + 2 * p;
    float xr, xi;
    xr = g_q[base]; xi = g_q[base + 1];
    g_q[base]     = xr * cs.x - xi * cs.y;
    g_q[base + 1] = xr * cs.y + xi * cs.x;
    xr = g_k[base]; xi = g_k[base + 1];
    g_k[base]     = xr * cs.x - xi * cs.y;
    g_k[base + 1] = xr * cs.y + xi * cs.x;
}

// ---------------- attention ----------------
__global__ __launch_bounds__(128)
void attn_kernel() {
    int sq = blockIdx.x;
    int bh = blockIdx.y;
    int b = bh / H_, h = bh - (bh / H_) * H_;
    int tid = threadIdx.x;
    __shared__ float qv[HD_];
    __shared__ float sc[S_];
    __shared__ float red[128];

    const float* qp = g_q + ((b * S_ + sq) * D_) + h * HD_;
    if (tid < HD_) qv[tid] = qp[tid];
    __syncthreads();

    for (int k = tid; k <= sq; k += 128) {
        const float4* kp = (const float4*)(g_k + ((b * S_ + k) * D_) + h * HD_);
        float d = 0.f;
#pragma unroll
        for (int j = 0; j < 16; j++) {
            float4 t = kp[j];
            d += qv[4 * j] * t.x + qv[4 * j + 1] * t.y + qv[4 * j + 2] * t.z + qv[4 * j + 3] * t.w;
        }
        sc[k] = d * 0.125f;
    }
    __syncthreads();

    float m = -1e30f;
    for (int k = tid; k <= sq; k += 128) m = fmaxf(m, sc[k]);
    red[tid] = m; __syncthreads();
    for (int st = 64; st > 0; st >>= 1) {
        if (tid < st) red[tid] = fmaxf(red[tid], red[tid + st]);
        __syncthreads();
    }
    m = red[0];
    __syncthreads();

    float ssum = 0.f;
    for (int k = tid; k <= sq; k += 128) { float p = expf(sc[k] - m); sc[k] = p; ssum += p; }
    red[tid] = ssum; __syncthreads();
    for (int st = 64; st > 0; st >>= 1) {
        if (tid < st) red[tid] += red[tid + st];
        __syncthreads();
    }
    float inv = 1.f / red[0];
    __syncthreads();

    int d = tid & 63, half = tid >> 6;
    float acc = 0.f;
    for (int k = half; k <= sq; k += 2)
        acc += sc[k] * g_v[((b * S_ + k) * D_) + h * HD_ + d];
    red[tid] = acc; __syncthreads();
    if (tid < HD_)
        g_o[((b * S_ + sq) * D_) + h * HD_ + tid] = (red[tid] + red[tid + 64]) * inv;
}

// ---------------- sparse BCE correction ----------------
__global__ void corr_kernel(const int* __restrict__ y) {
    int s = blockIdx.x * blockDim.x + threadIdx.x;
    if (s >= S_) return;
    int tok[2][FCS_];
    for (int b = 0; b < 2; b++)
        for (int j = 0; j < FCS_; j++)
            tok[b][j] = y[b * YW_ + (FCS_ - 1) + ((s - (FCS_ - 1) + j + S_) & (S_ - 1))];
    double dsum = 0.0;
    for (int b = 0; b < 2; b++)
        for (int j = 0; j < FCS_; j++) {
            int v = tok[b][j];
            bool first = true;
            for (int b2 = 0; b2 <= b && first; b2++) {
                int jmax = (b2 == b) ? j : FCS_;
                for (int j2 = 0; j2 < jmax; j2++)
                    if (tok[b2][j2] == v) { first = false; break; }
            }
            if (!first) continue;
            int c0 = 0, c1 = 0;
            for (int j2 = 0; j2 < FCS_; j2++) {
                c0 += (tok[0][j2] == v);
                c1 += (tok[1][j2] == v);
            }
            float w = (c0 > 1 || c1 > 1) ? 1.5f : 1.0f;
            for (int b2 = 0; b2 < 2; b2++) {
                float cv = g_c[((size_t)(b2 * S_ + s)) * V_ + v];
                float t  = ((b2 == 0 ? c0 : c1) > 0) ? 1.f : 0.f;
                dsum += (double)((w - 1.f) * softplusf(cv) - w * t * cv);
            }
        }
    atomicAdd(&g_acc[1], dsum);
}

// ---------------- logits += exp-kernel context (ring-buffer window) ----
// context[s] = sum_{d=1..8} e^(8-d) * c[s-d],  e = exp(-conv_w[0])
#define CTX_CHUNK 128
__global__ void ctx_scan_kernel(float* __restrict__ logits, const float* __restrict__ conv_w) {
    int v = blockIdx.x * blockDim.x + threadIdx.x;
    if (v >= V_) return;
    int b  = blockIdx.y;
    int s0 = blockIdx.z * CTX_CHUNK;     // multiple of 8
    float e = expf(-conv_w[0]);

    // pw[d-1] = e^(8-d): weight for lag d
    float pw[FCS_];
    pw[FCS_ - 1] = 1.f;
#pragma unroll
    for (int d = FCS_ - 1; d >= 1; --d) pw[d - 1] = pw[d] * e;

    // ring[s & 7] holds c[s]; prefill with c[s0-8 .. s0-1] (0 if s<0)
    float ring[FCS_];
#pragma unroll
    for (int j = 1; j <= FCS_; j++) {
        int sp = s0 - j;
        ring[(8 - j) & 7] = (sp >= 0) ? g_c[((size_t)(b * S_ + sp)) * V_ + v] : 0.f;
    }

    for (int t = 0; t < CTX_CHUNK / 8; t++) {
#pragma unroll
        for (int u = 0; u < 8; u++) {
            int s = s0 + 8 * t + u;
            size_t idx = ((size_t)(b * S_ + s)) * V_ + v;
            float ctx = 0.f;
#pragma unroll
            for (int d = 1; d <= FCS_; d++)
                ctx += pw[d - 1] * ring[(u - d) & 7];
            logits[idx] += ctx;
            ring[u] = g_c[idx];           // c[s] enters the window
        }
    }
}

// ---------------- NLL ----------------
__global__ void nll_kernel(const float* __restrict__ logits, const int* __restrict__ y) {
    int row = blockIdx.x;
    int b = row / S_, s = row - (row / S_) * S_;
    const float* lp = logits + (size_t)row * V_;
    __shared__ float red[256];
    float m = -1e30f;
    for (int v = threadIdx.x; v < V_; v += 256) m = fmaxf(m, lp[v]);
    red[threadIdx.x] = m; __syncthreads();
    for (int st = 128; st > 0; st >>= 1) {
        if (threadIdx.x < st) red[threadIdx.x] = fmaxf(red[threadIdx.x], red[threadIdx.x + st]);
        __syncthreads();
    }
    m = red[0];
    __syncthreads();
    float ssum = 0.f;
    for (int v = threadIdx.x; v < V_; v += 256) ssum += expf(lp[v] - m);
    red[threadIdx.x] = ssum; __syncthreads();
    for (int st = 128; st > 0; st >>= 1) {
        if (threadIdx.x < st) red[threadIdx.x] += red[threadIdx.x + st];
        __syncthreads();
    }
    if (threadIdx.x == 0) {
        int yt = y[b * YW_ + s];
        if (yt != -1) {
            float lse = m + logf(red[0]);
            atomicAdd(&g_acc[2], (double)(lse - lp[yt]));
            atomicAdd(&g_acc[3], 1.0);
        }
    }
}

__global__ void finalize_kernel(float* __restrict__ out) {
    double cnt = g_acc[3] < 1.0 ? 1.0 : g_acc[3];
    out[(size_t)NT_ * V_]     = (float)(g_acc[2] / cnt);
    out[(size_t)NT_ * V_ + 1] = (float)((g_acc[0] + g_acc[1]) / ((double)NT_ * (double)V_));
}

// ---------------- launcher ----------------
extern "C" void kernel_launch(void* const* d_in, const int* in_sizes, int n_in,
                              void* d_out, int out_size) {
    const int*   x      = (const int*)  d_in[0];
    const int*   y      = (const int*)  d_in[1];
    const float* emb    = (const float*)d_in[2];
    const float* wq     = (const float*)d_in[3];
    const float* wk     = (const float*)d_in[4];
    const float* wv     = (const float*)d_in[5];
    const float* wo     = (const float*)d_in[6];
    const float* w1     = (const float*)d_in[7];
    const float* w2     = (const float*)d_in[8];
    const float* w3     = (const float*)d_in[9];
    const float* attn_n = (const float*)d_in[10];
    const float* ffn_n  = (const float*)d_in[11];
    const float* out_n  = (const float*)d_in[12];
    const float* w_out  = (const float*)d_in[13];
    const float* w_ctx  = (const float*)d_in[14];
    const float* conv_w = (const float*)d_in[15];
    float* out = (float*)d_out;

    float *h_, *a_, *q_, *k_, *v_, *o_, *g1_, *u1_, *c_;
    cudaGetSymbolAddress((void**)&h_,  g_h);
    cudaGetSymbolAddress((void**)&a_,  g_a);
    cudaGetSymbolAddress((void**)&q_,  g_q);
    cudaGetSymbolAddress((void**)&k_,  g_k);
    cudaGetSymbolAddress((void**)&v_,  g_v);
    cudaGetSymbolAddress((void**)&o_,  g_o);
    cudaGetSymbolAddress((void**)&g1_, g_g1);
    cudaGetSymbolAddress((void**)&u1_, g_u1);
    cudaGetSymbolAddress((void**)&c_,  g_c);

    zero_acc_kernel<<<1, 32>>>();
    embed_kernel<<<(NT_ * D_ + 255) / 256, 256>>>(x, emb);
    rope_table_kernel<<<(S_ * 32 + 255) / 256, 256>>>();

    dim3 gQKV(D_ / 64, NT_ / 64, 3);     // 12 x 16 x 3
    dim3 gDs(D_ / 64, NT_ / 64);         // 12 x 16
    dim3 gF(F_ / 64, NT_ / 128);         // 32 x 8  (128x64 tiles)
    dim3 gTF(NT_ / 128, V_ / 128);       // 8 x 250 (m fast for L2 weight reuse)

    for (int i = 0; i < L_; i++) {
        const float* wq_i = wq + (size_t)i * D_ * D_;
        const float* wk_i = wk + (size_t)i * D_ * D_;
        const float* wv_i = wv + (size_t)i * D_ * D_;
        const float* wo_i = wo + (size_t)i * D_ * D_;
        const float* w1_i = w1 + (size_t)i * F_ * D_;
        const float* w2_i = w2 + (size_t)i * D_ * F_;
        const float* w3_i = w3 + (size_t)i * F_ * D_;

        rmsnorm_kernel<<<NT_, 256>>>(h_, attn_n + i * D_, a_);
        gemm_qkv<<<gQKV, 256>>>(a_, wq_i, wk_i, wv_i, q_, k_, v_, D_, D_);
        rope_apply_kernel<<<(B_ * S_ * H_ * 32 + 255) / 256, 256>>>();
        attn_kernel<<<dim3(S_, B_ * H_), 128>>>();
        gemm_k<64, 64, 4, 4, 1, 3><<<gDs, 256>>>(o_, wo_i, h_, nullptr, D_, D_);

        rmsnorm_kernel<<<NT_, 256>>>(h_, ffn_n + i * D_, a_);
        gemm_k<128, 64, 8, 4, 2, 2><<<gF, 256>>>(a_, w1_i, g1_, nullptr, F_, D_);
        gemm_k<128, 64, 8, 4, 3, 2><<<gF, 256>>>(a_, w3_i, u1_, g1_, F_, D_);
        gemm_k<64, 64, 4, 4, 1, 3><<<gDs, 256>>>(u1_, w2_i, h_, nullptr, D_, F_);
    }

    rmsnorm_kernel<<<NT_, 256>>>(h_, out_n, a_);
    gemm_tf32<0><<<gTF, 256>>>(a_, w_out, out, V_, D_);   // logits
    gemm_tf32<1><<<gTF, 256>>>(a_, w_ctx, c_,  V_, D_);   // c + softplus sum

    corr_kernel<<<(S_ + 255) / 256, 256>>>(y);
    ctx_scan_kernel<<<dim3((V_ + 255) / 256, B_, S_ / CTX_CHUNK), 256>>>(out, conv_w);
    nll_kernel<<<NT_, 256>>>(out, y);
    finalize_kernel<<<1, 1>>>(out);
}

// round 5
// speedup vs baseline: 1.4933x; 1.0000x over previous
#include <cuda_runtime.h>
#include <math.h>
#include <stdint.h>

#define B_  2
#define S_  512
#define V_  32000
#define D_  768
#define F_  2048
#define L_  4
#define H_  12
#define HD_ 64
#define FCS_ 8
#define YW_ (S_ + FCS_ - 1)   /* 519 */
#define NT_ (B_ * S_)         /* 1024 rows */

// ---------------- static scratch (allocation-free rule) ----------------
__device__ float  g_h [NT_ * D_];
__device__ float  g_a [NT_ * D_];
__device__ float  g_q [NT_ * D_];
__device__ float  g_k [NT_ * D_];
__device__ float  g_v [NT_ * D_];
__device__ float  g_o [NT_ * D_];
__device__ float  g_g1[NT_ * F_];
__device__ float  g_u1[NT_ * F_];
__device__ float  g_c [NT_ * V_];      // context head logits c (131 MB)
__device__ float2 g_rope[S_ * 32];
__device__ double g_acc[4];            // [0]=softplus_sum [1]=delta [2]=nll_sum [3]=valid

// ---------------- f32x2 packed helpers ----------------
typedef unsigned long long u64;

__device__ __forceinline__ u64 pk2(float lo, float hi) {
    u64 r; asm("mov.b64 %0, {%1, %2};" : "=l"(r) : "f"(lo), "f"(hi)); return r;
}
__device__ __forceinline__ void upk2(u64 v, float& lo, float& hi) {
    asm("mov.b64 {%0, %1}, %2;" : "=f"(lo), "=f"(hi) : "l"(v));
}
__device__ __forceinline__ u64 ffma2(u64 a, u64 b, u64 c) {
    u64 d; asm("fma.rn.f32x2 %0, %1, %2, %3;" : "=l"(d) : "l"(a), "l"(b), "l"(c)); return d;
}

__device__ __forceinline__ float softplusf(float x) {
    if (x > 15.0f) return x;
    return log1pf(expf(x));
}

__device__ __forceinline__ uint32_t f2tf32(float x) {
    uint32_t r; asm("cvt.rna.tf32.f32 %0, %1;" : "=r"(r) : "f"(x)); return r;
}

__device__ __forceinline__ void mma_tf32(float& c0, float& c1, float& c2, float& c3,
                                         uint32_t a0, uint32_t a1, uint32_t a2, uint32_t a3,
                                         uint32_t b0, uint32_t b1) {
    asm volatile("mma.sync.aligned.m16n8k8.row.col.f32.tf32.tf32.f32 "
                 "{%0,%1,%2,%3}, {%4,%5,%6,%7}, {%8,%9}, {%0,%1,%2,%3};"
                 : "+f"(c0), "+f"(c1), "+f"(c2), "+f"(c3)
                 : "r"(a0), "r"(a1), "r"(a2), "r"(a3), "r"(b0), "r"(b1));
}

__global__ void zero_acc_kernel() {
    if (threadIdx.x < 4) g_acc[threadIdx.x] = 0.0;
}

// ---------------- embedding gather ----------------
__global__ void embed_kernel(const int* __restrict__ x, const float* __restrict__ emb) {
    int i = blockIdx.x * blockDim.x + threadIdx.x;
    if (i >= NT_ * D_) return;
    int row = i / D_;
    int d   = i - row * D_;
    g_h[i] = emb[(size_t)x[row] * D_ + d];
}

// ---------------- rmsnorm ----------------
__global__ void rmsnorm_kernel(const float* __restrict__ in, const float* __restrict__ w,
                               float* __restrict__ out) {
    int row = blockIdx.x;
    const float* ip = in + row * D_;
    float* op = out + row * D_;
    __shared__ float red[256];
    float ss = 0.f;
    for (int d = threadIdx.x; d < D_; d += 256) { float v = ip[d]; ss += v * v; }
    red[threadIdx.x] = ss; __syncthreads();
    for (int st = 128; st > 0; st >>= 1) {
        if (threadIdx.x < st) red[threadIdx.x] += red[threadIdx.x + st];
        __syncthreads();
    }
    float rs = rsqrtf(red[0] / (float)D_ + 1e-5f);
    for (int d = threadIdx.x; d < D_; d += 256) op[d] = ip[d] * rs * w[d];
}

// =======================================================================
//  tf32 tensor-core NT-GEMM for the V-head projections.
//  C[m,n] = sum_k A[m,k]*W[n,k].  128x128 tile, 256 threads (2x4 warps,
//  64x32 warp tile), KT=16, fragments via m16n8k8 tf32 mma.
//  DOSP=1: also accumulate softplus(C) into g_acc[0].
// =======================================================================
#define TKT 16
#define TLD (TKT + 4)   /* smem row stride = 20 (conflict-free for frag loads) */

template<int DOSP>
__global__ __launch_bounds__(256, 2)
void gemm_tf32(const float* __restrict__ A, const float* __restrict__ Bw,
               float* __restrict__ C, int N, int K) {
    __shared__ uint32_t As[128][TLD];
    __shared__ uint32_t Bs[128][TLD];
    __shared__ float sred[256];

    const int tid  = threadIdx.x;
    const int lane = tid & 31;
    const int wid  = tid >> 5;
    const int wm   = wid >> 2;          // 0..1
    const int wn   = wid & 3;           // 0..3
    const int bm   = blockIdx.x * 128;  // m fast => weight-tile sharing in L2
    const int bn   = blockIdx.y * 128;

    const int lr = tid >> 1;            // 0..127
    const int ks = (tid & 1) * 8;       // 0 or 8
    const float* Ag = A  + (size_t)(bm + lr) * K + ks;
    const float* Bg = Bw + (size_t)(bn + lr) * K + ks;

    float acc[16][4];
#pragma unroll
    for (int i = 0; i < 16; i++)
#pragma unroll
        for (int j = 0; j < 4; j++) acc[i][j] = 0.f;

    float4 pa0 = *(const float4*)(Ag);
    float4 pa1 = *(const float4*)(Ag + 4);
    float4 pb0 = *(const float4*)(Bg);
    float4 pb1 = *(const float4*)(Bg + 4);

    const int nk = K / TKT;             // 48
    for (int kc = 0; kc < nk; kc++) {
        As[lr][ks + 0] = f2tf32(pa0.x); As[lr][ks + 1] = f2tf32(pa0.y);
        As[lr][ks + 2] = f2tf32(pa0.z); As[lr][ks + 3] = f2tf32(pa0.w);
        As[lr][ks + 4] = f2tf32(pa1.x); As[lr][ks + 5] = f2tf32(pa1.y);
        As[lr][ks + 6] = f2tf32(pa1.z); As[lr][ks + 7] = f2tf32(pa1.w);
        Bs[lr][ks + 0] = f2tf32(pb0.x); Bs[lr][ks + 1] = f2tf32(pb0.y);
        Bs[lr][ks + 2] = f2tf32(pb0.z); Bs[lr][ks + 3] = f2tf32(pb0.w);
        Bs[lr][ks + 4] = f2tf32(pb1.x); Bs[lr][ks + 5] = f2tf32(pb1.y);
        Bs[lr][ks + 6] = f2tf32(pb1.z); Bs[lr][ks + 7] = f2tf32(pb1.w);
        __syncthreads();

        if (kc + 1 < nk) {
            const float* Ap = Ag + (kc + 1) * TKT;
            const float* Bp = Bg + (kc + 1) * TKT;
            pa0 = *(const float4*)(Ap);
            pa1 = *(const float4*)(Ap + 4);
            pb0 = *(const float4*)(Bp);
            pb1 = *(const float4*)(Bp + 4);
        }

#pragma unroll
        for (int kk = 0; kk < 2; kk++) {
            const int kb = kk * 8;
            const int kq = kb + (lane & 3);
            uint32_t af[4][4], bf[4][2];
#pragma unroll
            for (int mt = 0; mt < 4; mt++) {
                int row = wm * 64 + mt * 16 + (lane >> 2);
                af[mt][0] = As[row][kq];
                af[mt][1] = As[row + 8][kq];
                af[mt][2] = As[row][kq + 4];
                af[mt][3] = As[row + 8][kq + 4];
            }
#pragma unroll
            for (int nt = 0; nt < 4; nt++) {
                int nr = wn * 32 + nt * 8 + (lane >> 2);
                bf[nt][0] = Bs[nr][kq];
                bf[nt][1] = Bs[nr][kq + 4];
            }
#pragma unroll
            for (int mt = 0; mt < 4; mt++)
#pragma unroll
                for (int nt = 0; nt < 4; nt++)
                    mma_tf32(acc[mt * 4 + nt][0], acc[mt * 4 + nt][1],
                             acc[mt * 4 + nt][2], acc[mt * 4 + nt][3],
                             af[mt][0], af[mt][1], af[mt][2], af[mt][3],
                             bf[nt][0], bf[nt][1]);
        }
        __syncthreads();
    }

    // ---------------- epilogue ----------------
    float spsum = 0.f;
#pragma unroll
    for (int mt = 0; mt < 4; mt++) {
        int r0 = bm + wm * 64 + mt * 16 + (lane >> 2);
#pragma unroll
        for (int nt = 0; nt < 4; nt++) {
            int cc = bn + wn * 32 + nt * 8 + (lane & 3) * 2;
            float* a4 = acc[mt * 4 + nt];
            *(float2*)(C + (size_t)r0 * N + cc)       = make_float2(a4[0], a4[1]);
            *(float2*)(C + (size_t)(r0 + 8) * N + cc) = make_float2(a4[2], a4[3]);
            if (DOSP)
                spsum += softplusf(a4[0]) + softplusf(a4[1]) +
                         softplusf(a4[2]) + softplusf(a4[3]);
        }
    }
    if (DOSP) {
        sred[tid] = spsum; __syncthreads();
        for (int st = 128; st > 0; st >>= 1) {
            if (tid < st) sred[tid] += sred[tid + st];
            __syncthreads();
        }
        if (tid == 0) atomicAdd(&g_acc[0], (double)sred[0]);
    }
}

// =======================================================================
//  f32x2 NT-GEMM (in-layer projections, verified fp32 path)
//  EPI: 0=store 1=add 2=silu 3=mulG
// =======================================================================
template<int BM, int BN, int TM, int TN, int EPI>
__device__ __forceinline__ void gemm_core(const float* __restrict__ A,
                                          const float* __restrict__ Bw,
                                          float* __restrict__ C,
                                          const float* __restrict__ G,
                                          int N, int K) {
    constexpr int KT  = 16;
    constexpr int LDA = BM + 4;
    constexpr int LDB = BN + 4;
    __shared__ float As[KT][LDA];
    __shared__ float Bs[KT][LDB];

    const int tid = threadIdx.x;
    constexpr int NTX = BN / TN;
    const int tx = tid % NTX;
    const int ty = tid / NTX;
    const int bm = blockIdx.y * BM;
    const int bn = blockIdx.x * BN;

    constexpr int NLA = (BM * KT) / (256 * 4);
    constexpr int NLB = (BN * KT) / (256 * 4);
    const int lrA = tid % BM, ksA = (tid / BM) * (4 * NLA);
    const int lrB = tid % BN, ksB = (tid / BN) * (4 * NLB);
    const float* Aldg = A  + (size_t)(bm + lrA) * K + ksA;
    const float* Bldg = Bw + (size_t)(bn + lrB) * K + ksB;

    float4 pa[NLA], pb[NLB];
#pragma unroll
    for (int l = 0; l < NLA; l++) pa[l] = *(const float4*)(Aldg + 4 * l);
#pragma unroll
    for (int l = 0; l < NLB; l++) pb[l] = *(const float4*)(Bldg + 4 * l);
#pragma unroll
    for (int l = 0; l < NLA; l++) {
        As[ksA + 4*l + 0][lrA] = pa[l].x; As[ksA + 4*l + 1][lrA] = pa[l].y;
        As[ksA + 4*l + 2][lrA] = pa[l].z; As[ksA + 4*l + 3][lrA] = pa[l].w;
    }
#pragma unroll
    for (int l = 0; l < NLB; l++) {
        Bs[ksB + 4*l + 0][lrB] = pb[l].x; Bs[ksB + 4*l + 1][lrB] = pb[l].y;
        Bs[ksB + 4*l + 2][lrB] = pb[l].z; Bs[ksB + 4*l + 3][lrB] = pb[l].w;
    }
    __syncthreads();

    u64 acc[TM / 2][TN];
#pragma unroll
    for (int i = 0; i < TM / 2; i++)
#pragma unroll
        for (int j = 0; j < TN; j++) acc[i][j] = 0ull;

    const int nk = K / KT;
    for (int kt = 0; kt < nk; kt++) {
        if (kt + 1 < nk) {
            const float* Ap = Aldg + (kt + 1) * KT;
            const float* Bp = Bldg + (kt + 1) * KT;
#pragma unroll
            for (int l = 0; l < NLA; l++) pa[l] = *(const float4*)(Ap + 4 * l);
#pragma unroll
            for (int l = 0; l < NLB; l++) pb[l] = *(const float4*)(Bp + 4 * l);
        }
#pragma unroll
        for (int k = 0; k < KT; k++) {
            u64 a2[TM / 2];
#pragma unroll
            for (int q = 0; q < TM / 4; q++) {
                float4 t = *(const float4*)&As[k][ty * TM + 4 * q];
                a2[2 * q]     = pk2(t.x, t.y);
                a2[2 * q + 1] = pk2(t.z, t.w);
            }
#pragma unroll
            for (int q = 0; q < TN / 4; q++) {
                float4 t = *(const float4*)&Bs[k][tx * TN + 4 * q];
                u64 b0 = pk2(t.x, t.x), b1 = pk2(t.y, t.y);
                u64 b2 = pk2(t.z, t.z), b3 = pk2(t.w, t.w);
#pragma unroll
                for (int i = 0; i < TM / 2; i++) {
                    acc[i][4*q + 0] = ffma2(a2[i], b0, acc[i][4*q + 0]);
                    acc[i][4*q + 1] = ffma2(a2[i], b1, acc[i][4*q + 1]);
                    acc[i][4*q + 2] = ffma2(a2[i], b2, acc[i][4*q + 2]);
                    acc[i][4*q + 3] = ffma2(a2[i], b3, acc[i][4*q + 3]);
                }
            }
        }
        __syncthreads();
        if (kt + 1 < nk) {
#pragma unroll
            for (int l = 0; l < NLA; l++) {
                As[ksA + 4*l + 0][lrA] = pa[l].x; As[ksA + 4*l + 1][lrA] = pa[l].y;
                As[ksA + 4*l + 2][lrA] = pa[l].z; As[ksA + 4*l + 3][lrA] = pa[l].w;
            }
#pragma unroll
            for (int l = 0; l < NLB; l++) {
                Bs[ksB + 4*l + 0][lrB] = pb[l].x; Bs[ksB + 4*l + 1][lrB] = pb[l].y;
                Bs[ksB + 4*l + 2][lrB] = pb[l].z; Bs[ksB + 4*l + 3][lrB] = pb[l].w;
            }
            __syncthreads();
        }
    }

    float spdummy = 0.f; (void)spdummy;
#pragma unroll
    for (int i = 0; i < TM; i++) {
        size_t idx = (size_t)(bm + ty * TM + i) * N + bn + tx * TN;
#pragma unroll
        for (int q = 0; q < TN / 4; q++) {
            float4 r;
            float lo, hi;
            upk2(acc[i >> 1][4*q + 0], lo, hi); r.x = (i & 1) ? hi : lo;
            upk2(acc[i >> 1][4*q + 1], lo, hi); r.y = (i & 1) ? hi : lo;
            upk2(acc[i >> 1][4*q + 2], lo, hi); r.z = (i & 1) ? hi : lo;
            upk2(acc[i >> 1][4*q + 3], lo, hi); r.w = (i & 1) ? hi : lo;
            if (EPI == 1) {
                float4 o = *(const float4*)(C + idx + 4 * q);
                r.x += o.x; r.y += o.y; r.z += o.z; r.w += o.w;
            } else if (EPI == 2) {
                r.x = r.x / (1.f + expf(-r.x));
                r.y = r.y / (1.f + expf(-r.y));
                r.z = r.z / (1.f + expf(-r.z));
                r.w = r.w / (1.f + expf(-r.w));
            } else if (EPI == 3) {
                float4 gg = *(const float4*)(G + idx + 4 * q);
                r.x *= gg.x; r.y *= gg.y; r.z *= gg.z; r.w *= gg.w;
            }
            *(float4*)(C + idx + 4 * q) = r;
        }
    }
}

template<int BM, int BN, int TM, int TN, int EPI, int OCC>
__global__ __launch_bounds__(256, OCC)
void gemm_k(const float* __restrict__ A, const float* __restrict__ Bw,
            float* __restrict__ C, const float* __restrict__ G, int N, int K) {
    gemm_core<BM, BN, TM, TN, EPI>(A, Bw, C, G, N, K);
}

// fused q/k/v: blockIdx.z selects weight + output
__global__ __launch_bounds__(256, 3)
void gemm_qkv(const float* __restrict__ A,
              const float* __restrict__ B0, const float* __restrict__ B1,
              const float* __restrict__ B2,
              float* __restrict__ C0, float* __restrict__ C1, float* __restrict__ C2,
              int N, int K) {
    const float* Bz = (blockIdx.z == 0) ? B0 : (blockIdx.z == 1) ? B1 : B2;
    float*       Cz = (blockIdx.z == 0) ? C0 : (blockIdx.z == 1) ? C1 : C2;
    gemm_core<64, 64, 4, 4, 0>(A, Bz, Cz, nullptr, N, K);
}

// ---------------- RoPE ----------------
__global__ void rope_table_kernel() {
    int i = blockIdx.x * blockDim.x + threadIdx.x;
    if (i >= S_ * 32) return;
    int s = i / 32, p = i - (i / 32) * 32;
    float f   = expf((float)(2 * p) * (-logf(10000.0f) / (float)HD_));
    float ang = (float)s * f;
    double a  = (double)ang;
    g_rope[i] = make_float2((float)cos(a), (float)sin(a));
}

__global__ void rope_apply_kernel() {
    int idx = blockIdx.x * blockDim.x + threadIdx.x;          // over B*S*H*32
    if (idx >= B_ * S_ * H_ * 32) return;
    int p = idx & 31;
    int h = (idx >> 5) % H_;
    int s = (idx / (32 * H_)) % S_;
    int b = idx / (32 * H_ * S_);
    float2 cs = g_rope[s * 32 + p];
    int base = ((b * S_ + s) * D_) + h * HD_ + 2 * p;
    float xr, xi;
    xr = g_q[base]; xi = g_q[base + 1];
    g_q[base]     = xr * cs.x - xi * cs.y;
    g_q[base + 1] = xr * cs.y + xi * cs.x;
    xr = g_k[base]; xi = g_k[base + 1];
    g_k[base]     = xr * cs.x - xi * cs.y;
    g_k[base + 1] = xr * cs.y + xi * cs.x;
}

// ---------------- attention ----------------
__global__ __launch_bounds__(128)
void attn_kernel() {
    int sq = blockIdx.x;
    int bh = blockIdx.y;
    int b = bh / H_, h = bh - (bh / H_) * H_;
    int tid = threadIdx.x;
    __shared__ float qv[HD_];
    __shared__ float sc[S_];
    __shared__ float red[128];

    const float* qp = g_q + ((b * S_ + sq) * D_) + h * HD_;
    if (tid < HD_) qv[tid] = qp[tid];
    __syncthreads();

    for (int k = tid; k <= sq; k += 128) {
        const float4* kp = (const float4*)(g_k + ((b * S_ + k) * D_) + h * HD_);
        float d = 0.f;
#pragma unroll
        for (int j = 0; j < 16; j++) {
            float4 t = kp[j];
            d += qv[4 * j] * t.x + qv[4 * j + 1] * t.y + qv[4 * j + 2] * t.z + qv[4 * j + 3] * t.w;
        }
        sc[k] = d * 0.125f;
    }
    __syncthreads();

    float m = -1e30f;
    for (int k = tid; k <= sq; k += 128) m = fmaxf(m, sc[k]);
    red[tid] = m; __syncthreads();
    for (int st = 64; st > 0; st >>= 1) {
        if (tid < st) red[tid] = fmaxf(red[tid], red[tid + st]);
        __syncthreads();
    }
    m = red[0];
    __syncthreads();

    float ssum = 0.f;
    for (int k = tid; k <= sq; k += 128) { float p = expf(sc[k] - m); sc[k] = p; ssum += p; }
    red[tid] = ssum; __syncthreads();
    for (int st = 64; st > 0; st >>= 1) {
        if (tid < st) red[tid] += red[tid + st];
        __syncthreads();
    }
    float inv = 1.f / red[0];
    __syncthreads();

    int d = tid & 63, half = tid >> 6;
    float acc = 0.f;
    for (int k = half; k <= sq; k += 2)
        acc += sc[k] * g_v[((b * S_ + k) * D_) + h * HD_ + d];
    red[tid] = acc; __syncthreads();
    if (tid < HD_)
        g_o[((b * S_ + sq) * D_) + h * HD_ + tid] = (red[tid] + red[tid + 64]) * inv;
}

// ---------------- sparse BCE correction ----------------
__global__ void corr_kernel(const int* __restrict__ y) {
    int s = blockIdx.x * blockDim.x + threadIdx.x;
    if (s >= S_) return;
    int tok[2][FCS_];
    for (int b = 0; b < 2; b++)
        for (int j = 0; j < FCS_; j++)
            tok[b][j] = y[b * YW_ + (FCS_ - 1) + ((s - (FCS_ - 1) + j + S_) & (S_ - 1))];
    double dsum = 0.0;
    for (int b = 0; b < 2; b++)
        for (int j = 0; j < FCS_; j++) {
            int v = tok[b][j];
            bool first = true;
            for (int b2 = 0; b2 <= b && first; b2++) {
                int jmax = (b2 == b) ? j : FCS_;
                for (int j2 = 0; j2 < jmax; j2++)
                    if (tok[b2][j2] == v) { first = false; break; }
            }
            if (!first) continue;
            int c0 = 0, c1 = 0;
            for (int j2 = 0; j2 < FCS_; j2++) {
                c0 += (tok[0][j2] == v);
                c1 += (tok[1][j2] == v);
            }
            float w = (c0 > 1 || c1 > 1) ? 1.5f : 1.0f;
            for (int b2 = 0; b2 < 2; b2++) {
                float cv = g_c[((size_t)(b2 * S_ + s)) * V_ + v];
                float t  = ((b2 == 0 ? c0 : c1) > 0) ? 1.f : 0.f;
                dsum += (double)((w - 1.f) * softplusf(cv) - w * t * cv);
            }
        }
    atomicAdd(&g_acc[1], dsum);
}

// ---------------- logits += exp-kernel context (ring-buffer window) ----
// context[s] = sum_{d=1..8} e^(8-d) * c[s-d],  e = exp(-conv_w[0])
#define CTX_CHUNK 128
__global__ void ctx_scan_kernel(float* __restrict__ logits, const float* __restrict__ conv_w) {
    int v = blockIdx.x * blockDim.x + threadIdx.x;
    if (v >= V_) return;
    int b  = blockIdx.y;
    int s0 = blockIdx.z * CTX_CHUNK;     // multiple of 8
    float e = expf(-conv_w[0]);

    // pw[d-1] = e^(8-d): weight for lag d
    float pw[FCS_];
    pw[FCS_ - 1] = 1.f;
#pragma unroll
    for (int d = FCS_ - 1; d >= 1; --d) pw[d - 1] = pw[d] * e;

    // ring[s & 7] holds c[s]; prefill with c[s0-8 .. s0-1] (0 if s<0)
    float ring[FCS_];
#pragma unroll
    for (int j = 1; j <= FCS_; j++) {
        int sp = s0 - j;
        ring[(8 - j) & 7] = (sp >= 0) ? g_c[((size_t)(b * S_ + sp)) * V_ + v] : 0.f;
    }

    for (int t = 0; t < CTX_CHUNK / 8; t++) {
#pragma unroll
        for (int u = 0; u < 8; u++) {
            int s = s0 + 8 * t + u;
            size_t idx = ((size_t)(b * S_ + s)) * V_ + v;
            float ctx = 0.f;
#pragma unroll
            for (int d = 1; d <= FCS_; d++)
                ctx += pw[d - 1] * ring[(u - d) & 7];
            logits[idx] += ctx;
            ring[u] = g_c[idx];           // c[s] enters the window
        }
    }
}

// ---------------- NLL ----------------
__global__ void nll_kernel(const float* __restrict__ logits, const int* __restrict__ y) {
    int row = blockIdx.x;
    int b = row / S_, s = row - (row / S_) * S_;
    const float* lp = logits + (size_t)row * V_;
    __shared__ float red[256];
    float m = -1e30f;
    for (int v = threadIdx.x; v < V_; v += 256) m = fmaxf(m, lp[v]);
    red[threadIdx.x] = m; __syncthreads();
    for (int st = 128; st > 0; st >>= 1) {
        if (threadIdx.x < st) red[threadIdx.x] = fmaxf(red[threadIdx.x], red[threadIdx.x + st]);
        __syncthreads();
    }
    m = red[0];
    __syncthreads();
    float ssum = 0.f;
    for (int v = threadIdx.x; v < V_; v += 256) ssum += expf(lp[v] - m);
    red[threadIdx.x] = ssum; __syncthreads();
    for (int st = 128; st > 0; st >>= 1) {
        if (threadIdx.x < st) red[threadIdx.x] += red[threadIdx.x + st];
        __syncthreads();
    }
    if (threadIdx.x == 0) {
        int yt = y[b * YW_ + s];
        if (yt != -1) {
            float lse = m + logf(red[0]);
            atomicAdd(&g_acc[2], (double)(lse - lp[yt]));
            atomicAdd(&g_acc[3], 1.0);
        }
    }
}

__global__ void finalize_kernel(float* __restrict__ out) {
    double cnt = g_acc[3] < 1.0 ? 1.0 : g_acc[3];
    out[(size_t)NT_ * V_]     = (float)(g_acc[2] / cnt);
    out[(size_t)NT_ * V_ + 1] = (float)((g_acc[0] + g_acc[1]) / ((double)NT_ * (double)V_));
}

// ---------------- launcher ----------------
extern "C" void kernel_launch(void* const* d_in, const int* in_sizes, int n_in,
                              void* d_out, int out_size) {
    const int*   x      = (const int*)  d_in[0];
    const int*   y      = (const int*)  d_in[1];
    const float* emb    = (const float*)d_in[2];
    const float* wq     = (const float*)d_in[3];
    const float* wk     = (const float*)d_in[4];
    const float* wv     = (const float*)d_in[5];
    const float* wo     = (const float*)d_in[6];
    const float* w1     = (const float*)d_in[7];
    const float* w2     = (const float*)d_in[8];
    const float* w3     = (const float*)d_in[9];
    const float* attn_n = (const float*)d_in[10];
    const float* ffn_n  = (const float*)d_in[11];
    const float* out_n  = (const float*)d_in[12];
    const float* w_out  = (const float*)d_in[13];
    const float* w_ctx  = (const float*)d_in[14];
    const float* conv_w = (const float*)d_in[15];
    float* out = (float*)d_out;

    float *h_, *a_, *q_, *k_, *v_, *o_, *g1_, *u1_, *c_;
    cudaGetSymbolAddress((void**)&h_,  g_h);
    cudaGetSymbolAddress((void**)&a_,  g_a);
    cudaGetSymbolAddress((void**)&q_,  g_q);
    cudaGetSymbolAddress((void**)&k_,  g_k);
    cudaGetSymbolAddress((void**)&v_,  g_v);
    cudaGetSymbolAddress((void**)&o_,  g_o);
    cudaGetSymbolAddress((void**)&g1_, g_g1);
    cudaGetSymbolAddress((void**)&u1_, g_u1);
    cudaGetSymbolAddress((void**)&c_,  g_c);

    zero_acc_kernel<<<1, 32>>>();
    embed_kernel<<<(NT_ * D_ + 255) / 256, 256>>>(x, emb);
    rope_table_kernel<<<(S_ * 32 + 255) / 256, 256>>>();

    dim3 gQKV(D_ / 64, NT_ / 64, 3);     // 12 x 16 x 3
    dim3 gDs(D_ / 64, NT_ / 64);         // 12 x 16
    dim3 gF(F_ / 64, NT_ / 128);         // 32 x 8  (128x64 tiles)
    dim3 gTF(NT_ / 128, V_ / 128);       // 8 x 250 (m fast for L2 weight reuse)

    for (int i = 0; i < L_; i++) {
        const float* wq_i = wq + (size_t)i * D_ * D_;
        const float* wk_i = wk + (size_t)i * D_ * D_;
        const float* wv_i = wv + (size_t)i * D_ * D_;
        const float* wo_i = wo + (size_t)i * D_ * D_;
        const float* w1_i = w1 + (size_t)i * F_ * D_;
        const float* w2_i = w2 + (size_t)i * D_ * F_;
        const float* w3_i = w3 + (size_t)i * F_ * D_;

        rmsnorm_kernel<<<NT_, 256>>>(h_, attn_n + i * D_, a_);
        gemm_qkv<<<gQKV, 256>>>(a_, wq_i, wk_i, wv_i, q_, k_, v_, D_, D_);
        rope_apply_kernel<<<(B_ * S_ * H_ * 32 + 255) / 256, 256>>>();
        attn_kernel<<<dim3(S_, B_ * H_), 128>>>();
        gemm_k<64, 64, 4, 4, 1, 3><<<gDs, 256>>>(o_, wo_i, h_, nullptr, D_, D_);

        rmsnorm_kernel<<<NT_, 256>>>(h_, ffn_n + i * D_, a_);
        gemm_k<128, 64, 8, 4, 2, 2><<<gF, 256>>>(a_, w1_i, g1_, nullptr, F_, D_);
        gemm_k<128, 64, 8, 4, 3, 2><<<gF, 256>>>(a_, w3_i, u1_, g1_, F_, D_);
        gemm_k<64, 64, 4, 4, 1, 3><<<gDs, 256>>>(u1_, w2_i, h_, nullptr, D_, F_);
    }

    rmsnorm_kernel<<<NT_, 256>>>(h_, out_n, a_);
    gemm_tf32<0><<<gTF, 256>>>(a_, w_out, out, V_, D_);   // logits
    gemm_tf32<1><<<gTF, 256>>>(a_, w_ctx, c_,  V_, D_);   // c + softplus sum

    corr_kernel<<<(S_ + 255) / 256, 256>>>(y);
    ctx_scan_kernel<<<dim3((V_ + 255) / 256, B_, S_ / CTX_CHUNK), 256>>>(out, conv_w);
    nll_kernel<<<NT_, 256>>>(out, y);
    finalize_kernel<<<1, 1>>>(out);
}

// round 6
// speedup vs baseline: 2.0481x; 1.3715x over previous
#include <cuda_runtime.h>
#include <math.h>
#include <stdint.h>

#define B_  2
#define S_  512
#define V_  32000
#define D_  768
#define F_  2048
#define L_  4
#define H_  12
#define HD_ 64
#define FCS_ 8
#define YW_ (S_ + FCS_ - 1)   /* 519 */
#define NT_ (B_ * S_)         /* 1024 rows */

// ---------------- static scratch (allocation-free rule) ----------------
__device__ float  g_h [NT_ * D_];
__device__ float  g_a [NT_ * D_];
__device__ float  g_q [NT_ * D_];
__device__ float  g_k [NT_ * D_];
__device__ float  g_v [NT_ * D_];
__device__ float  g_o [NT_ * D_];
__device__ float  g_g1[NT_ * F_];
__device__ float  g_u1[NT_ * F_];
__device__ float  g_c [NT_ * V_];      // context head logits c (131 MB)
__device__ float2 g_rope[S_ * 32];
__device__ double g_acc[4];            // [0]=softplus_sum [1]=delta [2]=nll_sum [3]=valid

__device__ __forceinline__ float softplusf(float x) {
    if (x > 15.0f) return x;
    return log1pf(expf(x));
}

__device__ __forceinline__ uint32_t f2tf32(float x) {
    uint32_t r; asm("cvt.rna.tf32.f32 %0, %1;" : "=r"(r) : "f"(x)); return r;
}

__device__ __forceinline__ void mma_tf32(float& c0, float& c1, float& c2, float& c3,
                                         uint32_t a0, uint32_t a1, uint32_t a2, uint32_t a3,
                                         uint32_t b0, uint32_t b1) {
    asm volatile("mma.sync.aligned.m16n8k8.row.col.f32.tf32.tf32.f32 "
                 "{%0,%1,%2,%3}, {%4,%5,%6,%7}, {%8,%9}, {%0,%1,%2,%3};"
                 : "+f"(c0), "+f"(c1), "+f"(c2), "+f"(c3)
                 : "r"(a0), "r"(a1), "r"(a2), "r"(a3), "r"(b0), "r"(b1));
}

__global__ void zero_acc_kernel() {
    if (threadIdx.x < 4) g_acc[threadIdx.x] = 0.0;
}

// ---------------- embedding gather ----------------
__global__ void embed_kernel(const int* __restrict__ x, const float* __restrict__ emb) {
    int i = blockIdx.x * blockDim.x + threadIdx.x;
    if (i >= NT_ * D_) return;
    int row = i / D_;
    int d   = i - row * D_;
    g_h[i] = emb[(size_t)x[row] * D_ + d];
}

// ---------------- rmsnorm ----------------
__global__ void rmsnorm_kernel(const float* __restrict__ in, const float* __restrict__ w,
                               float* __restrict__ out) {
    int row = blockIdx.x;
    const float* ip = in + row * D_;
    float* op = out + row * D_;
    __shared__ float red[256];
    float ss = 0.f;
    for (int d = threadIdx.x; d < D_; d += 256) { float v = ip[d]; ss += v * v; }
    red[threadIdx.x] = ss; __syncthreads();
    for (int st = 128; st > 0; st >>= 1) {
        if (threadIdx.x < st) red[threadIdx.x] += red[threadIdx.x + st];
        __syncthreads();
    }
    float rs = rsqrtf(red[0] / (float)D_ + 1e-5f);
    for (int d = threadIdx.x; d < D_; d += 256) op[d] = ip[d] * rs * w[d];
}

// =======================================================================
//  Generic tf32 tensor-core NT-GEMM:  C[m,n] (op)= sum_k A[m,k]*W[n,k]
//  BMxBN tile, WMxWN warp grid (THREADS = WM*WN*32), m16n8k8 mma,
//  KT=16 k-chunks, double-buffered smem, tf32 converted at gmem->smem.
//  EPI: 0=store 1=add(residual) 2=silu 3=mulG 4=store+softplus-sum
// =======================================================================
#define TLD 20   /* smem row stride: fragment loads conflict-free */

template<int BM, int BN, int WM, int WN, int EPI>
__device__ __forceinline__ void gemm_tc_core(const float* __restrict__ A,
                                             const float* __restrict__ Bw,
                                             float* __restrict__ C,
                                             const float* __restrict__ G,
                                             int N, int K,
                                             int bm, int bn) {
    constexpr int THREADS = WM * WN * 32;
    constexpr int WTM = BM / WM;        // warp tile m
    constexpr int WTN = BN / WN;        // warp tile n
    constexpr int MT  = WTM / 16;       // 16-row mma tiles per warp
    constexpr int NTT = WTN / 8;        // 8-col mma tiles per warp
    constexpr int RPP = THREADS / 2;    // rows loaded per pass
    constexpr int NLA = BM / RPP;
    constexpr int NLB = BN / RPP;

    __shared__ uint32_t As[2][BM][TLD];
    __shared__ uint32_t Bs[2][BN][TLD];
    __shared__ float sred[THREADS];

    const int tid  = threadIdx.x;
    const int lane = tid & 31;
    const int wid  = tid >> 5;
    const int wm   = wid / WN;
    const int wn   = wid % WN;

    const int lr = tid >> 1;            // base row within pass
    const int ks = (tid & 1) * 8;       // k offset 0/8
    const float* Ag = A  + (size_t)(bm + lr) * K + ks;
    const float* Bg = Bw + (size_t)(bn + lr) * K + ks;

    float acc[MT][NTT][4];
#pragma unroll
    for (int i = 0; i < MT; i++)
#pragma unroll
        for (int j = 0; j < NTT; j++)
#pragma unroll
            for (int q = 0; q < 4; q++) acc[i][j][q] = 0.f;

    float4 pa[NLA][2], pb[NLB][2];

#pragma unroll
    for (int l = 0; l < NLA; l++) {
        pa[l][0] = *(const float4*)(Ag + (size_t)l * RPP * K);
        pa[l][1] = *(const float4*)(Ag + (size_t)l * RPP * K + 4);
    }
#pragma unroll
    for (int l = 0; l < NLB; l++) {
        pb[l][0] = *(const float4*)(Bg + (size_t)l * RPP * K);
        pb[l][1] = *(const float4*)(Bg + (size_t)l * RPP * K + 4);
    }

    // store pass -> buffer
    auto store_tiles = [&](int buf) {
#pragma unroll
        for (int l = 0; l < NLA; l++) {
            uint4 u0 = make_uint4(f2tf32(pa[l][0].x), f2tf32(pa[l][0].y),
                                  f2tf32(pa[l][0].z), f2tf32(pa[l][0].w));
            uint4 u1 = make_uint4(f2tf32(pa[l][1].x), f2tf32(pa[l][1].y),
                                  f2tf32(pa[l][1].z), f2tf32(pa[l][1].w));
            *(uint4*)&As[buf][lr + l * RPP][ks]     = u0;
            *(uint4*)&As[buf][lr + l * RPP][ks + 4] = u1;
        }
#pragma unroll
        for (int l = 0; l < NLB; l++) {
            uint4 u0 = make_uint4(f2tf32(pb[l][0].x), f2tf32(pb[l][0].y),
                                  f2tf32(pb[l][0].z), f2tf32(pb[l][0].w));
            uint4 u1 = make_uint4(f2tf32(pb[l][1].x), f2tf32(pb[l][1].y),
                                  f2tf32(pb[l][1].z), f2tf32(pb[l][1].w));
            *(uint4*)&Bs[buf][lr + l * RPP][ks]     = u0;
            *(uint4*)&Bs[buf][lr + l * RPP][ks + 4] = u1;
        }
    };

    store_tiles(0);
    __syncthreads();

    const int nk = K / 16;
    for (int kc = 0; kc < nk; kc++) {
        const int cur = kc & 1;
        if (kc + 1 < nk) {
            const float* Ap = Ag + (kc + 1) * 16;
            const float* Bp = Bg + (kc + 1) * 16;
#pragma unroll
            for (int l = 0; l < NLA; l++) {
                pa[l][0] = *(const float4*)(Ap + (size_t)l * RPP * K);
                pa[l][1] = *(const float4*)(Ap + (size_t)l * RPP * K + 4);
            }
#pragma unroll
            for (int l = 0; l < NLB; l++) {
                pb[l][0] = *(const float4*)(Bp + (size_t)l * RPP * K);
                pb[l][1] = *(const float4*)(Bp + (size_t)l * RPP * K + 4);
            }
        }

#pragma unroll
        for (int kk = 0; kk < 2; kk++) {
            const int kq = kk * 8 + (lane & 3);
            uint32_t af[MT][4], bf[NTT][2];
#pragma unroll
            for (int mt = 0; mt < MT; mt++) {
                int row = wm * WTM + mt * 16 + (lane >> 2);
                af[mt][0] = As[cur][row][kq];
                af[mt][1] = As[cur][row + 8][kq];
                af[mt][2] = As[cur][row][kq + 4];
                af[mt][3] = As[cur][row + 8][kq + 4];
            }
#pragma unroll
            for (int nt = 0; nt < NTT; nt++) {
                int nr = wn * WTN + nt * 8 + (lane >> 2);
                bf[nt][0] = Bs[cur][nr][kq];
                bf[nt][1] = Bs[cur][nr][kq + 4];
            }
#pragma unroll
            for (int mt = 0; mt < MT; mt++)
#pragma unroll
                for (int nt = 0; nt < NTT; nt++)
                    mma_tf32(acc[mt][nt][0], acc[mt][nt][1],
                             acc[mt][nt][2], acc[mt][nt][3],
                             af[mt][0], af[mt][1], af[mt][2], af[mt][3],
                             bf[nt][0], bf[nt][1]);
        }

        if (kc + 1 < nk) store_tiles(cur ^ 1);
        __syncthreads();
    }

    // ---------------- epilogue ----------------
    float spsum = 0.f;
#pragma unroll
    for (int mt = 0; mt < MT; mt++) {
        int row = bm + wm * WTM + mt * 16 + (lane >> 2);
#pragma unroll
        for (int nt = 0; nt < NTT; nt++) {
            int col = bn + wn * WTN + nt * 8 + (lane & 3) * 2;
            float* a4 = acc[mt][nt];
            size_t i0 = (size_t)row * N + col;
            size_t i1 = (size_t)(row + 8) * N + col;
            float2 r0 = make_float2(a4[0], a4[1]);
            float2 r1 = make_float2(a4[2], a4[3]);
            if (EPI == 1) {
                float2 o0 = *(const float2*)(C + i0);
                float2 o1 = *(const float2*)(C + i1);
                r0.x += o0.x; r0.y += o0.y;
                r1.x += o1.x; r1.y += o1.y;
            } else if (EPI == 2) {
                r0.x = r0.x / (1.f + expf(-r0.x));
                r0.y = r0.y / (1.f + expf(-r0.y));
                r1.x = r1.x / (1.f + expf(-r1.x));
                r1.y = r1.y / (1.f + expf(-r1.y));
            } else if (EPI == 3) {
                float2 g0 = *(const float2*)(G + i0);
                float2 g1v = *(const float2*)(G + i1);
                r0.x *= g0.x; r0.y *= g0.y;
                r1.x *= g1v.x; r1.y *= g1v.y;
            } else if (EPI == 4) {
                spsum += softplusf(r0.x) + softplusf(r0.y) +
                         softplusf(r1.x) + softplusf(r1.y);
            }
            *(float2*)(C + i0) = r0;
            *(float2*)(C + i1) = r1;
        }
    }
    if (EPI == 4) {
        sred[tid] = spsum; __syncthreads();
        for (int st = THREADS / 2; st > 0; st >>= 1) {
            if (tid < st) sred[tid] += sred[tid + st];
            __syncthreads();
        }
        if (tid == 0) atomicAdd(&g_acc[0], (double)sred[0]);
    }
}

template<int BM, int BN, int WM, int WN, int EPI>
__global__ __launch_bounds__(WM * WN * 32)
void gemm_tc(const float* __restrict__ A, const float* __restrict__ Bw,
             float* __restrict__ C, const float* __restrict__ G, int N, int K) {
    gemm_tc_core<BM, BN, WM, WN, EPI>(A, Bw, C, G, N, K,
                                      blockIdx.x * BM, blockIdx.y * BN);
}

// fused q/k/v: blockIdx.z selects weight + output
__global__ __launch_bounds__(128)
void gemm_qkv_tc(const float* __restrict__ A,
                 const float* __restrict__ B0, const float* __restrict__ B1,
                 const float* __restrict__ B2,
                 float* __restrict__ C0, float* __restrict__ C1, float* __restrict__ C2,
                 int N, int K) {
    const float* Bz = (blockIdx.z == 0) ? B0 : (blockIdx.z == 1) ? B1 : B2;
    float*       Cz = (blockIdx.z == 0) ? C0 : (blockIdx.z == 1) ? C1 : C2;
    gemm_tc_core<64, 64, 2, 2, 0>(A, Bz, Cz, nullptr, N, K,
                                  blockIdx.x * 64, blockIdx.y * 64);
}

// ---------------- RoPE ----------------
__global__ void rope_table_kernel() {
    int i = blockIdx.x * blockDim.x + threadIdx.x;
    if (i >= S_ * 32) return;
    int s = i / 32, p = i - (i / 32) * 32;
    float f   = expf((float)(2 * p) * (-logf(10000.0f) / (float)HD_));
    float ang = (float)s * f;
    double a  = (double)ang;
    g_rope[i] = make_float2((float)cos(a), (float)sin(a));
}

__global__ void rope_apply_kernel() {
    int idx = blockIdx.x * blockDim.x + threadIdx.x;          // over B*S*H*32
    if (idx >= B_ * S_ * H_ * 32) return;
    int p = idx & 31;
    int h = (idx >> 5) % H_;
    int s = (idx / (32 * H_)) % S_;
    int b = idx / (32 * H_ * S_);
    float2 cs = g_rope[s * 32 + p];
    int base = ((b * S_ + s) * D_) + h * HD_ + 2 * p;
    float xr, xi;
    xr = g_q[base]; xi = g_q[base + 1];
    g_q[base]     = xr * cs.x - xi * cs.y;
    g_q[base + 1] = xr * cs.y + xi * cs.x;
    xr = g_k[base]; xi = g_k[base + 1];
    g_k[base]     = xr * cs.x - xi * cs.y;
    g_k[base + 1] = xr * cs.y + xi * cs.x;
}

// ---------------- attention ----------------
__global__ __launch_bounds__(128)
void attn_kernel() {
    int sq = blockIdx.x;
    int bh = blockIdx.y;
    int b = bh / H_, h = bh - (bh / H_) * H_;
    int tid = threadIdx.x;
    __shared__ float qv[HD_];
    __shared__ float sc[S_];
    __shared__ float red[128];

    const float* qp = g_q + ((b * S_ + sq) * D_) + h * HD_;
    if (tid < HD_) qv[tid] = qp[tid];
    __syncthreads();

    for (int k = tid; k <= sq; k += 128) {
        const float4* kp = (const float4*)(g_k + ((b * S_ + k) * D_) + h * HD_);
        float d = 0.f;
#pragma unroll
        for (int j = 0; j < 16; j++) {
            float4 t = kp[j];
            d += qv[4 * j] * t.x + qv[4 * j + 1] * t.y + qv[4 * j + 2] * t.z + qv[4 * j + 3] * t.w;
        }
        sc[k] = d * 0.125f;
    }
    __syncthreads();

    float m = -1e30f;
    for (int k = tid; k <= sq; k += 128) m = fmaxf(m, sc[k]);
    red[tid] = m; __syncthreads();
    for (int st = 64; st > 0; st >>= 1) {
        if (tid < st) red[tid] = fmaxf(red[tid], red[tid + st]);
        __syncthreads();
    }
    m = red[0];
    __syncthreads();

    float ssum = 0.f;
    for (int k = tid; k <= sq; k += 128) { float p = expf(sc[k] - m); sc[k] = p; ssum += p; }
    red[tid] = ssum; __syncthreads();
    for (int st = 64; st > 0; st >>= 1) {
        if (tid < st) red[tid] += red[tid + st];
        __syncthreads();
    }
    float inv = 1.f / red[0];
    __syncthreads();

    int d = tid & 63, half = tid >> 6;
    float acc = 0.f;
    for (int k = half; k <= sq; k += 2)
        acc += sc[k] * g_v[((b * S_ + k) * D_) + h * HD_ + d];
    red[tid] = acc; __syncthreads();
    if (tid < HD_)
        g_o[((b * S_ + sq) * D_) + h * HD_ + tid] = (red[tid] + red[tid + 64]) * inv;
}

// ---------------- sparse BCE correction ----------------
__global__ void corr_kernel(const int* __restrict__ y) {
    int s = blockIdx.x * blockDim.x + threadIdx.x;
    if (s >= S_) return;
    int tok[2][FCS_];
    for (int b = 0; b < 2; b++)
        for (int j = 0; j < FCS_; j++)
            tok[b][j] = y[b * YW_ + (FCS_ - 1) + ((s - (FCS_ - 1) + j + S_) & (S_ - 1))];
    double dsum = 0.0;
    for (int b = 0; b < 2; b++)
        for (int j = 0; j < FCS_; j++) {
            int v = tok[b][j];
            bool first = true;
            for (int b2 = 0; b2 <= b && first; b2++) {
                int jmax = (b2 == b) ? j : FCS_;
                for (int j2 = 0; j2 < jmax; j2++)
                    if (tok[b2][j2] == v) { first = false; break; }
            }
            if (!first) continue;
            int c0 = 0, c1 = 0;
            for (int j2 = 0; j2 < FCS_; j2++) {
                c0 += (tok[0][j2] == v);
                c1 += (tok[1][j2] == v);
            }
            float w = (c0 > 1 || c1 > 1) ? 1.5f : 1.0f;
            for (int b2 = 0; b2 < 2; b2++) {
                float cv = g_c[((size_t)(b2 * S_ + s)) * V_ + v];
                float t  = ((b2 == 0 ? c0 : c1) > 0) ? 1.f : 0.f;
                dsum += (double)((w - 1.f) * softplusf(cv) - w * t * cv);
            }
        }
    atomicAdd(&g_acc[1], dsum);
}

// ---------------- logits += exp-kernel context (ring-buffer window) ----
// context[s] = sum_{d=1..8} e^(8-d) * c[s-d],  e = exp(-conv_w[0])
#define CTX_CHUNK 128
__global__ void ctx_scan_kernel(float* __restrict__ logits, const float* __restrict__ conv_w) {
    int v = blockIdx.x * blockDim.x + threadIdx.x;
    if (v >= V_) return;
    int b  = blockIdx.y;
    int s0 = blockIdx.z * CTX_CHUNK;     // multiple of 8
    float e = expf(-conv_w[0]);

    // pw[d-1] = e^(8-d): weight for lag d
    float pw[FCS_];
    pw[FCS_ - 1] = 1.f;
#pragma unroll
    for (int d = FCS_ - 1; d >= 1; --d) pw[d - 1] = pw[d] * e;

    // ring[s & 7] holds c[s]; prefill with c[s0-8 .. s0-1] (0 if s<0)
    float ring[FCS_];
#pragma unroll
    for (int j = 1; j <= FCS_; j++) {
        int sp = s0 - j;
        ring[(8 - j) & 7] = (sp >= 0) ? g_c[((size_t)(b * S_ + sp)) * V_ + v] : 0.f;
    }

    for (int t = 0; t < CTX_CHUNK / 8; t++) {
#pragma unroll
        for (int u = 0; u < 8; u++) {
            int s = s0 + 8 * t + u;
            size_t idx = ((size_t)(b * S_ + s)) * V_ + v;
            float ctx = 0.f;
#pragma unroll
            for (int d = 1; d <= FCS_; d++)
                ctx += pw[d - 1] * ring[(u - d) & 7];
            logits[idx] += ctx;
            ring[u] = g_c[idx];           // c[s] enters the window
        }
    }
}

// ---------------- NLL ----------------
__global__ void nll_kernel(const float* __restrict__ logits, const int* __restrict__ y) {
    int row = blockIdx.x;
    int b = row / S_, s = row - (row / S_) * S_;
    const float* lp = logits + (size_t)row * V_;
    __shared__ float red[256];
    float m = -1e30f;
    for (int v = threadIdx.x; v < V_; v += 256) m = fmaxf(m, lp[v]);
    red[threadIdx.x] = m; __syncthreads();
    for (int st = 128; st > 0; st >>= 1) {
        if (threadIdx.x < st) red[threadIdx.x] = fmaxf(red[threadIdx.x], red[threadIdx.x + st]);
        __syncthreads();
    }
    m = red[0];
    __syncthreads();
    float ssum = 0.f;
    for (int v = threadIdx.x; v < V_; v += 256) ssum += expf(lp[v] - m);
    red[threadIdx.x] = ssum; __syncthreads();
    for (int st = 128; st > 0; st >>= 1) {
        if (threadIdx.x < st) red[threadIdx.x] += red[threadIdx.x + st];
        __syncthreads();
    }
    if (threadIdx.x == 0) {
        int yt = y[b * YW_ + s];
        if (yt != -1) {
            float lse = m + logf(red[0]);
            atomicAdd(&g_acc[2], (double)(lse - lp[yt]));
            atomicAdd(&g_acc[3], 1.0);
        }
    }
}

__global__ void finalize_kernel(float* __restrict__ out) {
    double cnt = g_acc[3] < 1.0 ? 1.0 : g_acc[3];
    out[(size_t)NT_ * V_]     = (float)(g_acc[2] / cnt);
    out[(size_t)NT_ * V_ + 1] = (float)((g_acc[0] + g_acc[1]) / ((double)NT_ * (double)V_));
}

// ---------------- launcher ----------------
extern "C" void kernel_launch(void* const* d_in, const int* in_sizes, int n_in,
                              void* d_out, int out_size) {
    const int*   x      = (const int*)  d_in[0];
    const int*   y      = (const int*)  d_in[1];
    const float* emb    = (const float*)d_in[2];
    const float* wq     = (const float*)d_in[3];
    const float* wk     = (const float*)d_in[4];
    const float* wv     = (const float*)d_in[5];
    const float* wo     = (const float*)d_in[6];
    const float* w1     = (const float*)d_in[7];
    const float* w2     = (const float*)d_in[8];
    const float* w3     = (const float*)d_in[9];
    const float* attn_n = (const float*)d_in[10];
    const float* ffn_n  = (const float*)d_in[11];
    const float* out_n  = (const float*)d_in[12];
    const float* w_out  = (const float*)d_in[13];
    const float* w_ctx  = (const float*)d_in[14];
    const float* conv_w = (const float*)d_in[15];
    float* out = (float*)d_out;

    float *h_, *a_, *q_, *k_, *v_, *o_, *g1_, *u1_, *c_;
    cudaGetSymbolAddress((void**)&h_,  g_h);
    cudaGetSymbolAddress((void**)&a_,  g_a);
    cudaGetSymbolAddress((void**)&q_,  g_q);
    cudaGetSymbolAddress((void**)&k_,  g_k);
    cudaGetSymbolAddress((void**)&v_,  g_v);
    cudaGetSymbolAddress((void**)&o_,  g_o);
    cudaGetSymbolAddress((void**)&g1_, g_g1);
    cudaGetSymbolAddress((void**)&u1_, g_u1);
    cudaGetSymbolAddress((void**)&c_,  g_c);

    zero_acc_kernel<<<1, 32>>>();
    embed_kernel<<<(NT_ * D_ + 255) / 256, 256>>>(x, emb);
    rope_table_kernel<<<(S_ * 32 + 255) / 256, 256>>>();

    dim3 gQKV(NT_ / 64, D_ / 64, 3);     // 16 x 12 x 3 (64x64 tiles)
    dim3 gDs (NT_ / 64, D_ / 64);        // 16 x 12
    dim3 gF  (NT_ / 128, F_ / 64);       // 8 x 32 (128x64 tiles)
    dim3 gTF (NT_ / 128, V_ / 128);      // 8 x 250 (m fast for L2 weight reuse)

    for (int i = 0; i < L_; i++) {
        const float* wq_i = wq + (size_t)i * D_ * D_;
        const float* wk_i = wk + (size_t)i * D_ * D_;
        const float* wv_i = wv + (size_t)i * D_ * D_;
        const float* wo_i = wo + (size_t)i * D_ * D_;
        const float* w1_i = w1 + (size_t)i * F_ * D_;
        const float* w2_i = w2 + (size_t)i * D_ * F_;
        const float* w3_i = w3 + (size_t)i * F_ * D_;

        rmsnorm_kernel<<<NT_, 256>>>(h_, attn_n + i * D_, a_);
        gemm_qkv_tc<<<gQKV, 128>>>(a_, wq_i, wk_i, wv_i, q_, k_, v_, D_, D_);
        rope_apply_kernel<<<(B_ * S_ * H_ * 32 + 255) / 256, 256>>>();
        attn_kernel<<<dim3(S_, B_ * H_), 128>>>();
        gemm_tc<64, 64, 2, 2, 1><<<gDs, 128>>>(o_, wo_i, h_, nullptr, D_, D_);

        rmsnorm_kernel<<<NT_, 256>>>(h_, ffn_n + i * D_, a_);
        gemm_tc<128, 64, 2, 2, 2><<<gF, 128>>>(a_, w1_i, g1_, nullptr, F_, D_);
        gemm_tc<128, 64, 2, 2, 3><<<gF, 128>>>(a_, w3_i, u1_, g1_, F_, D_);
        gemm_tc<64, 64, 2, 2, 1><<<gDs, 128>>>(u1_, w2_i, h_, nullptr, D_, F_);
    }

    rmsnorm_kernel<<<NT_, 256>>>(h_, out_n, a_);
    gemm_tc<128, 128, 2, 4, 0><<<gTF, 256>>>(a_, w_out, out, nullptr, V_, D_);  // logits
    gemm_tc<128, 128, 2, 4, 4><<<gTF, 256>>>(a_, w_ctx, c_,  nullptr, V_, D_);  // c + softplus

    corr_kernel<<<(S_ + 255) / 256, 256>>>(y);
    ctx_scan_kernel<<<dim3((V_ + 255) / 256, B_, S_ / CTX_CHUNK), 256>>>(out, conv_w);
    nll_kernel<<<NT_, 256>>>(out, y);
    finalize_kernel<<<1, 1>>>(out);
}